// round 13
// baseline (speedup 1.0000x reference)
#include <cuda_runtime.h>
#include <cuda_bf16.h>
#include <cstdint>

#define N_NODES  100000
#define N_EDGES  1600000
#define HIDDEN   128
#define IN_FEAT  7
#define N_GRAPHS 512
#define N_TOTAL_E (N_EDGES + N_NODES)
#define SCAN_BLOCKS ((N_NODES + 1023) / 1024)   // 98

// ---------------- scratch ----------------
__device__ int   d_deg[N_NODES];
__device__ float d_dis[N_NODES];
__device__ float d_xs[(size_t)N_NODES * 8];     // padded to 8 floats/row (32B aligned)
__device__ int   d_rowptr[N_NODES + 1];
__device__ int   d_bsum[SCAN_BLOCKS];
__device__ int   d_cursor[N_NODES];
__device__ int   d_csr_src[N_TOTAL_E];
__device__ __nv_bfloat16 d_h1[(size_t)N_NODES * HIDDEN];
__device__ __nv_bfloat16 d_h2[(size_t)N_NODES * HIDDEN];
__device__ float d_agg[(size_t)N_NODES * HIDDEN];
__device__ float d_pool[N_GRAPHS * HIDDEN];
__device__ __nv_bfloat16 d_wthi[2][HIDDEN * HIDDEN];   // W^T hi (bf16), [n][k]

// ---------------- helpers ----------------
__device__ __forceinline__ uint32_t smem_u32(const void* p) {
    uint32_t a;
    asm("{ .reg .u64 t; cvta.to.shared.u64 t, %1; cvt.u32.u64 %0, t; }" : "=r"(a) : "l"(p));
    return a;
}

// XOR-16B swizzled byte offset inside a [rows][256B] bf16 tile
#define SWZ(row, kb) ((uint32_t)((row) * 256 + ((kb) ^ (((row) & 7) << 4))))

#define LDMATRIX_X4(r0, r1, r2, r3, addr) \
    asm volatile("ldmatrix.sync.aligned.m8n8.x4.shared.b16 {%0,%1,%2,%3}, [%4];" \
        : "=r"(r0), "=r"(r1), "=r"(r2), "=r"(r3) : "r"(addr))

#define MMA_BF16(c0, c1, c2, c3, a0, a1, a2, a3, b0, b1) \
    asm volatile("mma.sync.aligned.m16n8k16.row.col.f32.bf16.bf16.f32 " \
        "{%0,%1,%2,%3}, {%4,%5,%6,%7}, {%8,%9}, {%0,%1,%2,%3};" \
        : "+f"(c0), "+f"(c1), "+f"(c2), "+f"(c3) \
        : "r"(a0), "r"(a1), "r"(a2), "r"(a3), "r"(b0), "r"(b1))

// ---------------- setup ----------------
__global__ void k_degree(const int* __restrict__ dst) {
    int i = blockIdx.x * blockDim.x + threadIdx.x;
    int base = i * 4;
    if (base + 3 < N_EDGES) {
        int4 d4 = *(const int4*)&dst[base];
        atomicAdd(&d_deg[d4.x], 1);
        atomicAdd(&d_deg[d4.y], 1);
        atomicAdd(&d_deg[d4.z], 1);
        atomicAdd(&d_deg[d4.w], 1);
    } else {
        for (int e = base; e < N_EDGES; e++) atomicAdd(&d_deg[dst[e]], 1);
    }
}

__global__ void k_dis_scanpart(const float* __restrict__ x) {
    __shared__ int wsum[32];
    int tid = threadIdx.x, lane = tid & 31, wid = tid >> 5;
    int i = blockIdx.x * 1024 + tid;
    int v = 0;
    if (i < N_NODES) {
        v = d_deg[i] + 1;
        float d = rsqrtf((float)v);
        d_dis[i] = d;
        float4 q0, q1;
        q0.x = d * x[(size_t)i * IN_FEAT + 0];
        q0.y = d * x[(size_t)i * IN_FEAT + 1];
        q0.z = d * x[(size_t)i * IN_FEAT + 2];
        q0.w = d * x[(size_t)i * IN_FEAT + 3];
        q1.x = d * x[(size_t)i * IN_FEAT + 4];
        q1.y = d * x[(size_t)i * IN_FEAT + 5];
        q1.z = d * x[(size_t)i * IN_FEAT + 6];
        q1.w = 0.f;
        *(float4*)&d_xs[(size_t)i * 8]     = q0;
        *(float4*)&d_xs[(size_t)i * 8 + 4] = q1;
    }
    int xx = v;
    #pragma unroll
    for (int o = 1; o < 32; o <<= 1) {
        int y = __shfl_up_sync(0xffffffffu, xx, o);
        if (lane >= o) xx += y;
    }
    if (lane == 31) wsum[wid] = xx;
    __syncthreads();
    if (wid == 0) {
        int s = wsum[lane];
        #pragma unroll
        for (int o = 1; o < 32; o <<= 1) {
            int y = __shfl_up_sync(0xffffffffu, s, o);
            if (lane >= o) s += y;
        }
        wsum[lane] = s;
    }
    __syncthreads();
    int excl = (wid > 0 ? wsum[wid - 1] : 0) + xx - v;
    if (i < N_NODES) d_rowptr[i] = excl;
    if (tid == 1023) d_bsum[blockIdx.x] = wsum[31];
}

__global__ void k_scan_finish() {
    __shared__ int soff;
    if (threadIdx.x == 0) {
        int a = 0;
        for (int k = 0; k < blockIdx.x; k++) a += d_bsum[k];
        soff = a;
    }
    __syncthreads();
    int i = blockIdx.x * 1024 + threadIdx.x;
    if (i < N_NODES) {
        int rp = d_rowptr[i] + soff;
        d_rowptr[i] = rp;
        d_cursor[i] = rp + 1;
        d_csr_src[rp] = i;
    }
    if (blockIdx.x == 0 && threadIdx.x == 0) d_rowptr[N_NODES] = N_TOTAL_E;
}

__global__ void k_fill_edges(const int* __restrict__ src, const int* __restrict__ dst) {
    int i = blockIdx.x * blockDim.x + threadIdx.x;
    int base = i * 4;
    if (base + 3 < N_EDGES) {
        int4 d4 = *(const int4*)&dst[base];
        int4 s4 = *(const int4*)&src[base];
        int p0 = atomicAdd(&d_cursor[d4.x], 1);
        int p1 = atomicAdd(&d_cursor[d4.y], 1);
        int p2 = atomicAdd(&d_cursor[d4.z], 1);
        int p3 = atomicAdd(&d_cursor[d4.w], 1);
        d_csr_src[p0] = s4.x;
        d_csr_src[p1] = s4.y;
        d_csr_src[p2] = s4.z;
        d_csr_src[p3] = s4.w;
    } else {
        for (int e = base; e < N_EDGES; e++) {
            int p = atomicAdd(&d_cursor[dst[e]], 1);
            d_csr_src[p] = src[e];
        }
    }
}

// W^T bf16 precompute + zero-init of deg/pool: grid (128, 2), block 128
__global__ void k_prep_w(const float* __restrict__ W2, const float* __restrict__ W3) {
    int n = blockIdx.x, k = threadIdx.x, L = blockIdx.y;
    const float* W = (L == 0) ? W2 : W3;
    d_wthi[L][n * HIDDEN + k] = __float2bfloat16(W[k * HIDDEN + n]);
    int gt = (L * 128 + n) * 128 + k;          // 0..32767
    #pragma unroll
    for (int r = 0; r < 2; r++) {
        int p = gt + r * 32768;
        if (p < N_GRAPHS * HIDDEN) d_pool[p] = 0.f;
    }
    #pragma unroll
    for (int r = 0; r < 4; r++) {
        int p = gt + r * 32768;
        if (p < N_NODES) d_deg[p] = 0;
    }
}

// ---------------- layer 1: lane-per-edge gather + warp reduce + 7->128 GEMM ----------------
__global__ void k_layer1(const float* __restrict__ W1, const float* __restrict__ b1) {
    __shared__ float sW[IN_FEAT * HIDDEN];
    __shared__ float sb[HIDDEN];
    int tid = threadIdx.x;
    for (int i = tid; i < IN_FEAT * HIDDEN; i += 256) sW[i] = W1[i];
    if (tid < HIDDEN) sb[tid] = b1[tid];
    __syncthreads();

    int warp = (blockIdx.x * 256 + tid) >> 5;
    int lane = tid & 31;
    if (warp >= N_NODES) return;

    int beg = d_rowptr[warp], end = d_rowptr[warp + 1];
    float a[8];
    #pragma unroll
    for (int j = 0; j < 8; j++) a[j] = 0.f;

    for (int e = beg + lane; e < end; e += 32) {
        int s = d_csr_src[e];
        float4 q0 = *(const float4*)&d_xs[(size_t)s * 8];
        float4 q1 = *(const float4*)&d_xs[(size_t)s * 8 + 4];
        a[0] += q0.x; a[1] += q0.y; a[2] += q0.z; a[3] += q0.w;
        a[4] += q1.x; a[5] += q1.y; a[6] += q1.z; a[7] += q1.w;
    }
    #pragma unroll
    for (int o = 16; o > 0; o >>= 1) {
        #pragma unroll
        for (int j = 0; j < IN_FEAT; j++)
            a[j] += __shfl_xor_sync(0xffffffffu, a[j], o);
    }

    float dd = d_dis[warp];
    #pragma unroll
    for (int j = 0; j < IN_FEAT; j++) a[j] *= dd;

    int c0 = lane * 4;
    float4 o;
    o.x = sb[c0]; o.y = sb[c0 + 1]; o.z = sb[c0 + 2]; o.w = sb[c0 + 3];
    #pragma unroll
    for (int j = 0; j < IN_FEAT; j++) {
        o.x += a[j] * sW[j * HIDDEN + c0];
        o.y += a[j] * sW[j * HIDDEN + c0 + 1];
        o.z += a[j] * sW[j * HIDDEN + c0 + 2];
        o.w += a[j] * sW[j * HIDDEN + c0 + 3];
    }
    o.x = fmaxf(o.x, 0.f) * dd; o.y = fmaxf(o.y, 0.f) * dd;
    o.z = fmaxf(o.z, 0.f) * dd; o.w = fmaxf(o.w, 0.f) * dd;
    __nv_bfloat162 p[2];
    p[0] = __floats2bfloat162_rn(o.x, o.y);
    p[1] = __floats2bfloat162_rn(o.z, o.w);
    *(uint2*)&d_h1[(size_t)warp * HIDDEN + c0] = *(uint2*)p;
}

// ---------------- aggregation (bf16 in, fp32 out), 8-deep MLP ----------------
__global__ void k_aggregate(const __nv_bfloat16* __restrict__ hin, float* __restrict__ gout) {
    int warp = (blockIdx.x * blockDim.x + threadIdx.x) >> 5;
    int lane = threadIdx.x & 31;
    if (warp >= N_NODES) return;
    int beg = d_rowptr[warp], end = d_rowptr[warp + 1];
    float4 acc = make_float4(0.f, 0.f, 0.f, 0.f);
    float4 acc2 = make_float4(0.f, 0.f, 0.f, 0.f);
    int fo = lane * 4;
    for (int e0 = beg; e0 < end; e0 += 32) {
        int e = e0 + lane;
        int s = (e < end) ? d_csr_src[e] : 0;
        int cnt = min(32, end - e0);
        int j = 0;
        for (; j + 7 < cnt; j += 8) {
            int s0 = __shfl_sync(0xffffffffu, s, j);
            int s1 = __shfl_sync(0xffffffffu, s, j + 1);
            int s2 = __shfl_sync(0xffffffffu, s, j + 2);
            int s3 = __shfl_sync(0xffffffffu, s, j + 3);
            int s4 = __shfl_sync(0xffffffffu, s, j + 4);
            int s5 = __shfl_sync(0xffffffffu, s, j + 5);
            int s6 = __shfl_sync(0xffffffffu, s, j + 6);
            int s7 = __shfl_sync(0xffffffffu, s, j + 7);
            uint2 u0 = *(const uint2*)&hin[(size_t)s0 * HIDDEN + fo];
            uint2 u1 = *(const uint2*)&hin[(size_t)s1 * HIDDEN + fo];
            uint2 u2 = *(const uint2*)&hin[(size_t)s2 * HIDDEN + fo];
            uint2 u3 = *(const uint2*)&hin[(size_t)s3 * HIDDEN + fo];
            uint2 u4 = *(const uint2*)&hin[(size_t)s4 * HIDDEN + fo];
            uint2 u5 = *(const uint2*)&hin[(size_t)s5 * HIDDEN + fo];
            uint2 u6 = *(const uint2*)&hin[(size_t)s6 * HIDDEN + fo];
            uint2 u7 = *(const uint2*)&hin[(size_t)s7 * HIDDEN + fo];
            float2 a0 = __bfloat1622float2(*(__nv_bfloat162*)&u0.x);
            float2 b0 = __bfloat1622float2(*(__nv_bfloat162*)&u0.y);
            float2 a1 = __bfloat1622float2(*(__nv_bfloat162*)&u1.x);
            float2 b1 = __bfloat1622float2(*(__nv_bfloat162*)&u1.y);
            float2 a2 = __bfloat1622float2(*(__nv_bfloat162*)&u2.x);
            float2 b2 = __bfloat1622float2(*(__nv_bfloat162*)&u2.y);
            float2 a3 = __bfloat1622float2(*(__nv_bfloat162*)&u3.x);
            float2 b3 = __bfloat1622float2(*(__nv_bfloat162*)&u3.y);
            float2 a4 = __bfloat1622float2(*(__nv_bfloat162*)&u4.x);
            float2 b4 = __bfloat1622float2(*(__nv_bfloat162*)&u4.y);
            float2 a5 = __bfloat1622float2(*(__nv_bfloat162*)&u5.x);
            float2 b5 = __bfloat1622float2(*(__nv_bfloat162*)&u5.y);
            float2 a6 = __bfloat1622float2(*(__nv_bfloat162*)&u6.x);
            float2 b6 = __bfloat1622float2(*(__nv_bfloat162*)&u6.y);
            float2 a7 = __bfloat1622float2(*(__nv_bfloat162*)&u7.x);
            float2 b7 = __bfloat1622float2(*(__nv_bfloat162*)&u7.y);
            acc.x  += (a0.x + a1.x) + (a2.x + a3.x);
            acc.y  += (a0.y + a1.y) + (a2.y + a3.y);
            acc.z  += (b0.x + b1.x) + (b2.x + b3.x);
            acc.w  += (b0.y + b1.y) + (b2.y + b3.y);
            acc2.x += (a4.x + a5.x) + (a6.x + a7.x);
            acc2.y += (a4.y + a5.y) + (a6.y + a7.y);
            acc2.z += (b4.x + b5.x) + (b6.x + b7.x);
            acc2.w += (b4.y + b5.y) + (b6.y + b7.y);
        }
        for (; j + 3 < cnt; j += 4) {
            int s0 = __shfl_sync(0xffffffffu, s, j);
            int s1 = __shfl_sync(0xffffffffu, s, j + 1);
            int s2 = __shfl_sync(0xffffffffu, s, j + 2);
            int s3 = __shfl_sync(0xffffffffu, s, j + 3);
            uint2 u0 = *(const uint2*)&hin[(size_t)s0 * HIDDEN + fo];
            uint2 u1 = *(const uint2*)&hin[(size_t)s1 * HIDDEN + fo];
            uint2 u2 = *(const uint2*)&hin[(size_t)s2 * HIDDEN + fo];
            uint2 u3 = *(const uint2*)&hin[(size_t)s3 * HIDDEN + fo];
            float2 a0 = __bfloat1622float2(*(__nv_bfloat162*)&u0.x);
            float2 b0 = __bfloat1622float2(*(__nv_bfloat162*)&u0.y);
            float2 a1 = __bfloat1622float2(*(__nv_bfloat162*)&u1.x);
            float2 b1 = __bfloat1622float2(*(__nv_bfloat162*)&u1.y);
            float2 a2 = __bfloat1622float2(*(__nv_bfloat162*)&u2.x);
            float2 b2 = __bfloat1622float2(*(__nv_bfloat162*)&u2.y);
            float2 a3 = __bfloat1622float2(*(__nv_bfloat162*)&u3.x);
            float2 b3 = __bfloat1622float2(*(__nv_bfloat162*)&u3.y);
            acc.x += (a0.x + a1.x) + (a2.x + a3.x);
            acc.y += (a0.y + a1.y) + (a2.y + a3.y);
            acc.z += (b0.x + b1.x) + (b2.x + b3.x);
            acc.w += (b0.y + b1.y) + (b2.y + b3.y);
        }
        for (; j < cnt; j++) {
            int s0 = __shfl_sync(0xffffffffu, s, j);
            uint2 u0 = *(const uint2*)&hin[(size_t)s0 * HIDDEN + fo];
            float2 a0 = __bfloat1622float2(*(__nv_bfloat162*)&u0.x);
            float2 b0 = __bfloat1622float2(*(__nv_bfloat162*)&u0.y);
            acc.x += a0.x; acc.y += a0.y; acc.z += b0.x; acc.w += b0.y;
        }
    }
    float dd = d_dis[warp];
    acc.x = (acc.x + acc2.x) * dd;
    acc.y = (acc.y + acc2.y) * dd;
    acc.z = (acc.z + acc2.z) * dd;
    acc.w = (acc.w + acc2.w) * dd;
    *(float4*)&gout[(size_t)warp * HIDDEN + fo] = acc;
}

// ---------------- HMMA GEMM: 64-row tile, 2-pass A-split (A_hi+A_lo) x W_hi ----------------
// mode=0: hout(bf16) = relu(G@W+b)*dis   |   mode=1: fused segment-max pooling
#define OFF_BIAS 0
#define OFF_AHI  1024
#define OFF_ALO  (1024 + 16384)
#define OFF_BHI  (1024 + 32768)
#define GEMM_MMA_SMEM (1024 + 32768 + 32768)

__global__ __launch_bounds__(256, 2)
void k_gemm_mma(const float* __restrict__ G, int wsel,
                const float* __restrict__ bias,
                __nv_bfloat16* __restrict__ hout,
                const int* __restrict__ batch, int mode) {
    extern __shared__ char smem[];
    uint32_t sbase = smem_u32(smem);
    float* sbias = (float*)(smem + OFF_BIAS);
    int tid = threadIdx.x, lane = tid & 31, wid = tid >> 5;
    int row0 = blockIdx.x * 64;

    if (tid < HIDDEN) sbias[tid] = bias[tid];

    // stage B: W^T hi [128 n][256B], swizzled
    {
        const uint4* bh = (const uint4*)&d_wthi[wsel][0];
        #pragma unroll
        for (int i = 0; i < 8; i++) {
            int v = tid + 256 * i;
            int n = v >> 4, c16 = v & 15;
            uint32_t off = SWZ(n, c16 * 16);
            *(uint4*)(smem + OFF_BHI + off) = bh[v];
        }
    }
    // stage A: 64 rows of fp32 G -> bf16 hi/lo, swizzled
    {
        const float4* G4 = (const float4*)G;
        #pragma unroll
        for (int i = 0; i < 4; i++) {
            int v = tid + 256 * i;
            int r = v >> 4, c16 = v & 15;
            int row = row0 + r;
            float f[8] = {0.f, 0.f, 0.f, 0.f, 0.f, 0.f, 0.f, 0.f};
            if (row < N_NODES) {
                float4 q0 = G4[(size_t)row * 32 + c16 * 2];
                float4 q1 = G4[(size_t)row * 32 + c16 * 2 + 1];
                f[0] = q0.x; f[1] = q0.y; f[2] = q0.z; f[3] = q0.w;
                f[4] = q1.x; f[5] = q1.y; f[6] = q1.z; f[7] = q1.w;
            }
            __nv_bfloat162 hi[4], lo[4];
            #pragma unroll
            for (int j = 0; j < 4; j++) {
                __nv_bfloat16 h0 = __float2bfloat16(f[2 * j]);
                __nv_bfloat16 h1 = __float2bfloat16(f[2 * j + 1]);
                hi[j] = __nv_bfloat162(h0, h1);
                lo[j] = __floats2bfloat162_rn(f[2 * j] - __bfloat162float(h0),
                                              f[2 * j + 1] - __bfloat162float(h1));
            }
            uint32_t off = SWZ(r, c16 * 16);
            *(uint4*)(smem + OFF_AHI + off) = *(uint4*)hi;
            *(uint4*)(smem + OFF_ALO + off) = *(uint4*)lo;
        }
    }
    __syncthreads();

    int mi = wid >> 1;          // m-tile 0..3
    int nb = (wid & 1) * 64;    // n-half

    int a_row = mi * 16 + (lane & 7) + ((lane >> 3) & 1) * 8;
    int a_kx  = ((lane >> 4) & 1) * 16;
    uint32_t a_base = sbase + (uint32_t)(a_row * 256);
    int a_swz = (a_row & 7) << 4;

    int b_row = nb + (lane & 7) + ((lane & 16) ? 8 : 0);
    int b_kx  = (lane & 8) ? 16 : 0;
    int b_swz = (b_row & 7) << 4;

    float acc[8][4];
    #pragma unroll
    for (int nt = 0; nt < 8; nt++)
        #pragma unroll
        for (int j = 0; j < 4; j++) acc[nt][j] = 0.f;

    const uint32_t a_offs[2] = {OFF_AHI, OFF_ALO};

    #pragma unroll
    for (int p = 0; p < 2; p++) {
        uint32_t abase = a_base + a_offs[p];
        #pragma unroll
        for (int ks = 0; ks < 8; ks++) {
            int kb = ks * 32;
            uint32_t a0r, a1r, a2r, a3r;
            LDMATRIX_X4(a0r, a1r, a2r, a3r, abase + (uint32_t)((kb + a_kx) ^ a_swz));
            uint32_t b[16];
            #pragma unroll
            for (int j = 0; j < 4; j++) {
                uint32_t addr = sbase + OFF_BHI + (uint32_t)((b_row + j * 16) * 256)
                              + (uint32_t)((kb + b_kx) ^ b_swz);
                LDMATRIX_X4(b[4 * j], b[4 * j + 1], b[4 * j + 2], b[4 * j + 3], addr);
            }
            #pragma unroll
            for (int nt = 0; nt < 8; nt++)
                MMA_BF16(acc[nt][0], acc[nt][1], acc[nt][2], acc[nt][3],
                         a0r, a1r, a2r, a3r, b[2 * nt], b[2 * nt + 1]);
        }
    }

    int q = lane & 3, rq = lane >> 2;
    int rA = mi * 16 + rq;          // local rows
    int rB = rA + 8;
    int rowA = row0 + rA;
    int rowB = row0 + rB;

    if (mode == 0) {
        float scA = (rowA < N_NODES) ? d_dis[rowA] : 1.f;
        float scB = (rowB < N_NODES) ? d_dis[rowB] : 1.f;
        #pragma unroll
        for (int nt = 0; nt < 8; nt++) {
            int col = nb + nt * 8 + 2 * q;
            float bc0 = sbias[col], bc1 = sbias[col + 1];
            if (rowA < N_NODES) {
                __nv_bfloat162 v = __floats2bfloat162_rn(fmaxf(acc[nt][0] + bc0, 0.f) * scA,
                                                         fmaxf(acc[nt][1] + bc1, 0.f) * scA);
                *(uint32_t*)&hout[(size_t)rowA * HIDDEN + col] = *(uint32_t*)&v;
            }
            if (rowB < N_NODES) {
                __nv_bfloat162 v = __floats2bfloat162_rn(fmaxf(acc[nt][2] + bc0, 0.f) * scB,
                                                         fmaxf(acc[nt][3] + bc1, 0.f) * scB);
                *(uint32_t*)&hout[(size_t)rowB * HIDDEN + col] = *(uint32_t*)&v;
            }
        }
    } else {
        // fused pooling: stage relu values into smem, run-length segment-max + atomicMax
        __syncthreads();
        float* spool = (float*)(smem + OFF_AHI);     // [64][128] fp32 = 32 KB
        int* sbatch = (int*)(smem + OFF_BHI);        // 64 ints
        #pragma unroll
        for (int nt = 0; nt < 8; nt++) {
            int col = nb + nt * 8 + 2 * q;
            float bc0 = sbias[col], bc1 = sbias[col + 1];
            spool[rA * HIDDEN + col]     = fmaxf(acc[nt][0] + bc0, 0.f);
            spool[rA * HIDDEN + col + 1] = fmaxf(acc[nt][1] + bc1, 0.f);
            spool[rB * HIDDEN + col]     = fmaxf(acc[nt][2] + bc0, 0.f);
            spool[rB * HIDDEN + col + 1] = fmaxf(acc[nt][3] + bc1, 0.f);
        }
        if (tid < 64 && row0 + tid < N_NODES) sbatch[tid] = batch[row0 + tid];
        __syncthreads();
        if (tid < HIDDEN) {
            int cur = -1; float run = 0.f;
            #pragma unroll 4
            for (int r = 0; r < 64; r++) {
                if (row0 + r >= N_NODES) break;
                int g = sbatch[r];
                float v = spool[r * HIDDEN + tid];
                if (g != cur) {
                    if (cur >= 0)
                        atomicMax((int*)&d_pool[cur * HIDDEN + tid], __float_as_int(run));
                    cur = g; run = v;
                } else {
                    run = fmaxf(run, v);
                }
            }
            if (cur >= 0)
                atomicMax((int*)&d_pool[cur * HIDDEN + tid], __float_as_int(run));
        }
    }
}

// ---------------- final ----------------
__global__ void k_final(const float* __restrict__ Wl, const float* __restrict__ bl,
                        float* __restrict__ out) {
    __shared__ float sW[HIDDEN * 2];
    __shared__ float sb[2];
    int tid = threadIdx.x;
    if (tid < HIDDEN * 2) sW[tid] = Wl[tid];
    if (tid < 2) sb[tid] = bl[tid];
    __syncthreads();
    if (tid < N_GRAPHS) {
        float a0 = sb[0], a1 = sb[1];
        #pragma unroll 8
        for (int k = 0; k < HIDDEN; k++) {
            float p = d_pool[tid * HIDDEN + k];
            a0 += p * sW[k * 2 + 0];
            a1 += p * sW[k * 2 + 1];
        }
        out[tid * 2 + 0] = a0;
        out[tid * 2 + 1] = a1;
    }
}

// ---------------- launcher ----------------
extern "C" void kernel_launch(void* const* d_in, const int* in_sizes, int n_in,
                              void* d_out, int out_size) {
    const float* x     = (const float*)d_in[0];
    const int*   ei    = (const int*)  d_in[1];
    const int*   batch = (const int*)  d_in[2];
    const float* W1 = (const float*)d_in[3];
    const float* b1 = (const float*)d_in[4];
    const float* W2 = (const float*)d_in[5];
    const float* b2 = (const float*)d_in[6];
    const float* W3 = (const float*)d_in[7];
    const float* b3 = (const float*)d_in[8];
    const float* Wl = (const float*)d_in[9];
    const float* bl = (const float*)d_in[10];
    float* out = (float*)d_out;

    const int* src = ei;
    const int* dst = ei + N_EDGES;

    __nv_bfloat16* h1; cudaGetSymbolAddress((void**)&h1, d_h1);
    __nv_bfloat16* h2; cudaGetSymbolAddress((void**)&h2, d_h2);
    float* agg;  cudaGetSymbolAddress((void**)&agg, d_agg);

    cudaFuncSetAttribute(k_gemm_mma, cudaFuncAttributeMaxDynamicSharedMemorySize, GEMM_MMA_SMEM);

    const int TPB = 256;

    k_prep_w      <<<dim3(128, 2), 128>>>(W2, W3);   // also zeroes d_deg / d_pool
    k_degree      <<<(N_EDGES / 4 + TPB - 1) / TPB, TPB>>>(dst);
    k_dis_scanpart<<<SCAN_BLOCKS, 1024>>>(x);
    k_scan_finish <<<SCAN_BLOCKS, 1024>>>();
    k_fill_edges  <<<(N_EDGES / 4 + TPB - 1) / TPB, TPB>>>(src, dst);

    // layer 1 -> h1 (bf16, dis-prescaled)
    k_layer1<<<(N_NODES * 32 + TPB - 1) / TPB, TPB>>>(W1, b1);

    // layer 2: agg = A h1 ; h2 = bf16(relu(agg W2 + b2) * dis)
    k_aggregate<<<(N_NODES * 32 + TPB - 1) / TPB, TPB>>>(h1, agg);
    k_gemm_mma<<<(N_NODES + 63) / 64, 256, GEMM_MMA_SMEM>>>(agg, 0, b2, h2, batch, 0);

    // layer 3: agg = A h2 ; fused GEMM + segment-max pooling
    k_aggregate<<<(N_NODES * 32 + TPB - 1) / TPB, TPB>>>(h2, agg);
    k_gemm_mma<<<(N_NODES + 63) / 64, 256, GEMM_MMA_SMEM>>>(agg, 1, b3, nullptr, batch, 1);

    k_final<<<1, 512>>>(Wl, bl, out);
}

// round 14
// speedup vs baseline: 1.2270x; 1.2270x over previous
#include <cuda_runtime.h>
#include <cuda_bf16.h>
#include <cstdint>

#define N_NODES  100000
#define N_EDGES  1600000
#define HIDDEN   128
#define IN_FEAT  7
#define N_GRAPHS 512
#define N_TOTAL_E (N_EDGES + N_NODES)
#define SCAN_BLOCKS ((N_NODES + 1023) / 1024)   // 98

// ---------------- scratch ----------------
__device__ int   d_deg[N_NODES];
__device__ float d_dis[N_NODES];
__device__ float d_xs[(size_t)N_NODES * 8];     // padded to 8 floats/row (32B aligned)
__device__ int   d_rowptr[N_NODES + 1];
__device__ int   d_bsum[SCAN_BLOCKS];
__device__ int   d_cursor[N_NODES];
__device__ int   d_csr_src[N_TOTAL_E];
__device__ __nv_bfloat16 d_h1[(size_t)N_NODES * HIDDEN];
__device__ __nv_bfloat16 d_h2[(size_t)N_NODES * HIDDEN];
__device__ float d_agg[(size_t)N_NODES * HIDDEN];
__device__ float d_pool[N_GRAPHS * HIDDEN];
__device__ __nv_bfloat16 d_wthi[2][HIDDEN * HIDDEN];   // W^T hi (bf16), [n][k]

// ---------------- helpers ----------------
__device__ __forceinline__ uint32_t smem_u32(const void* p) {
    uint32_t a;
    asm("{ .reg .u64 t; cvta.to.shared.u64 t, %1; cvt.u32.u64 %0, t; }" : "=r"(a) : "l"(p));
    return a;
}

// XOR-16B swizzled byte offset inside a [rows][256B] bf16 tile
#define SWZ(row, kb) ((uint32_t)((row) * 256 + ((kb) ^ (((row) & 7) << 4))))

#define LDMATRIX_X4(r0, r1, r2, r3, addr) \
    asm volatile("ldmatrix.sync.aligned.m8n8.x4.shared.b16 {%0,%1,%2,%3}, [%4];" \
        : "=r"(r0), "=r"(r1), "=r"(r2), "=r"(r3) : "r"(addr))

#define MMA_BF16(c0, c1, c2, c3, a0, a1, a2, a3, b0, b1) \
    asm volatile("mma.sync.aligned.m16n8k16.row.col.f32.bf16.bf16.f32 " \
        "{%0,%1,%2,%3}, {%4,%5,%6,%7}, {%8,%9}, {%0,%1,%2,%3};" \
        : "+f"(c0), "+f"(c1), "+f"(c2), "+f"(c3) \
        : "r"(a0), "r"(a1), "r"(a2), "r"(a3), "r"(b0), "r"(b1))

// ---------------- setup ----------------
__global__ void k_degree(const int* __restrict__ dst) {
    int i = blockIdx.x * blockDim.x + threadIdx.x;
    int base = i * 4;
    if (base + 3 < N_EDGES) {
        int4 d4 = *(const int4*)&dst[base];
        atomicAdd(&d_deg[d4.x], 1);
        atomicAdd(&d_deg[d4.y], 1);
        atomicAdd(&d_deg[d4.z], 1);
        atomicAdd(&d_deg[d4.w], 1);
    } else {
        for (int e = base; e < N_EDGES; e++) atomicAdd(&d_deg[dst[e]], 1);
    }
}

__global__ void k_dis_scanpart(const float* __restrict__ x) {
    __shared__ int wsum[32];
    int tid = threadIdx.x, lane = tid & 31, wid = tid >> 5;
    int i = blockIdx.x * 1024 + tid;
    int v = 0;
    if (i < N_NODES) {
        v = d_deg[i] + 1;
        float d = rsqrtf((float)v);
        d_dis[i] = d;
        float4 q0, q1;
        q0.x = d * x[(size_t)i * IN_FEAT + 0];
        q0.y = d * x[(size_t)i * IN_FEAT + 1];
        q0.z = d * x[(size_t)i * IN_FEAT + 2];
        q0.w = d * x[(size_t)i * IN_FEAT + 3];
        q1.x = d * x[(size_t)i * IN_FEAT + 4];
        q1.y = d * x[(size_t)i * IN_FEAT + 5];
        q1.z = d * x[(size_t)i * IN_FEAT + 6];
        q1.w = 0.f;
        *(float4*)&d_xs[(size_t)i * 8]     = q0;
        *(float4*)&d_xs[(size_t)i * 8 + 4] = q1;
    }
    int xx = v;
    #pragma unroll
    for (int o = 1; o < 32; o <<= 1) {
        int y = __shfl_up_sync(0xffffffffu, xx, o);
        if (lane >= o) xx += y;
    }
    if (lane == 31) wsum[wid] = xx;
    __syncthreads();
    if (wid == 0) {
        int s = wsum[lane];
        #pragma unroll
        for (int o = 1; o < 32; o <<= 1) {
            int y = __shfl_up_sync(0xffffffffu, s, o);
            if (lane >= o) s += y;
        }
        wsum[lane] = s;
    }
    __syncthreads();
    int excl = (wid > 0 ? wsum[wid - 1] : 0) + xx - v;
    if (i < N_NODES) d_rowptr[i] = excl;
    if (tid == 1023) d_bsum[blockIdx.x] = wsum[31];
}

__global__ void k_scan_finish() {
    __shared__ int soff;
    if (threadIdx.x == 0) {
        int a = 0;
        for (int k = 0; k < blockIdx.x; k++) a += d_bsum[k];
        soff = a;
    }
    __syncthreads();
    int i = blockIdx.x * 1024 + threadIdx.x;
    if (i < N_NODES) {
        int rp = d_rowptr[i] + soff;
        d_rowptr[i] = rp;
        d_cursor[i] = rp + 1;
        d_csr_src[rp] = i;
    }
    if (blockIdx.x == 0 && threadIdx.x == 0) d_rowptr[N_NODES] = N_TOTAL_E;
}

__global__ void k_fill_edges(const int* __restrict__ src, const int* __restrict__ dst) {
    int i = blockIdx.x * blockDim.x + threadIdx.x;
    if (i < N_EDGES) {
        int d = dst[i];
        int p = atomicAdd(&d_cursor[d], 1);
        d_csr_src[p] = src[i];
    }
}

// W^T bf16 precompute + zero-init of deg/pool: grid (128, 2), block 128
__global__ void k_prep_w(const float* __restrict__ W2, const float* __restrict__ W3) {
    int n = blockIdx.x, k = threadIdx.x, L = blockIdx.y;
    const float* W = (L == 0) ? W2 : W3;
    d_wthi[L][n * HIDDEN + k] = __float2bfloat16(W[k * HIDDEN + n]);
    int gt = (L * 128 + n) * 128 + k;          // 0..32767
    #pragma unroll
    for (int r = 0; r < 2; r++) {
        int p = gt + r * 32768;
        if (p < N_GRAPHS * HIDDEN) d_pool[p] = 0.f;
    }
    #pragma unroll
    for (int r = 0; r < 4; r++) {
        int p = gt + r * 32768;
        if (p < N_NODES) d_deg[p] = 0;
    }
}

// ---------------- layer 1: lane-per-edge gather + warp reduce + 7->128 GEMM ----------------
__global__ void k_layer1(const float* __restrict__ W1, const float* __restrict__ b1) {
    __shared__ float sW[IN_FEAT * HIDDEN];
    __shared__ float sb[HIDDEN];
    int tid = threadIdx.x;
    for (int i = tid; i < IN_FEAT * HIDDEN; i += 256) sW[i] = W1[i];
    if (tid < HIDDEN) sb[tid] = b1[tid];
    __syncthreads();

    int warp = (blockIdx.x * 256 + tid) >> 5;
    int lane = tid & 31;
    if (warp >= N_NODES) return;

    int beg = d_rowptr[warp], end = d_rowptr[warp + 1];
    float a[8];
    #pragma unroll
    for (int j = 0; j < 8; j++) a[j] = 0.f;

    for (int e = beg + lane; e < end; e += 32) {
        int s = d_csr_src[e];
        float4 q0 = *(const float4*)&d_xs[(size_t)s * 8];
        float4 q1 = *(const float4*)&d_xs[(size_t)s * 8 + 4];
        a[0] += q0.x; a[1] += q0.y; a[2] += q0.z; a[3] += q0.w;
        a[4] += q1.x; a[5] += q1.y; a[6] += q1.z; a[7] += q1.w;
    }
    #pragma unroll
    for (int o = 16; o > 0; o >>= 1) {
        #pragma unroll
        for (int j = 0; j < IN_FEAT; j++)
            a[j] += __shfl_xor_sync(0xffffffffu, a[j], o);
    }

    float dd = d_dis[warp];
    #pragma unroll
    for (int j = 0; j < IN_FEAT; j++) a[j] *= dd;

    int c0 = lane * 4;
    float4 o;
    o.x = sb[c0]; o.y = sb[c0 + 1]; o.z = sb[c0 + 2]; o.w = sb[c0 + 3];
    #pragma unroll
    for (int j = 0; j < IN_FEAT; j++) {
        o.x += a[j] * sW[j * HIDDEN + c0];
        o.y += a[j] * sW[j * HIDDEN + c0 + 1];
        o.z += a[j] * sW[j * HIDDEN + c0 + 2];
        o.w += a[j] * sW[j * HIDDEN + c0 + 3];
    }
    o.x = fmaxf(o.x, 0.f) * dd; o.y = fmaxf(o.y, 0.f) * dd;
    o.z = fmaxf(o.z, 0.f) * dd; o.w = fmaxf(o.w, 0.f) * dd;
    __nv_bfloat162 p[2];
    p[0] = __floats2bfloat162_rn(o.x, o.y);
    p[1] = __floats2bfloat162_rn(o.z, o.w);
    *(uint2*)&d_h1[(size_t)warp * HIDDEN + c0] = *(uint2*)p;
}

// ---------------- aggregation (bf16 in, fp32 out) ----------------
__global__ void k_aggregate(const __nv_bfloat16* __restrict__ hin, float* __restrict__ gout) {
    int warp = (blockIdx.x * blockDim.x + threadIdx.x) >> 5;
    int lane = threadIdx.x & 31;
    if (warp >= N_NODES) return;
    int beg = d_rowptr[warp], end = d_rowptr[warp + 1];
    float4 acc = make_float4(0.f, 0.f, 0.f, 0.f);
    int fo = lane * 4;
    for (int e0 = beg; e0 < end; e0 += 32) {
        int e = e0 + lane;
        int s = (e < end) ? d_csr_src[e] : 0;
        int cnt = min(32, end - e0);
        int j = 0;
        for (; j + 3 < cnt; j += 4) {
            int s0 = __shfl_sync(0xffffffffu, s, j);
            int s1 = __shfl_sync(0xffffffffu, s, j + 1);
            int s2 = __shfl_sync(0xffffffffu, s, j + 2);
            int s3 = __shfl_sync(0xffffffffu, s, j + 3);
            uint2 u0 = *(const uint2*)&hin[(size_t)s0 * HIDDEN + fo];
            uint2 u1 = *(const uint2*)&hin[(size_t)s1 * HIDDEN + fo];
            uint2 u2 = *(const uint2*)&hin[(size_t)s2 * HIDDEN + fo];
            uint2 u3 = *(const uint2*)&hin[(size_t)s3 * HIDDEN + fo];
            float2 a0 = __bfloat1622float2(*(__nv_bfloat162*)&u0.x);
            float2 b0 = __bfloat1622float2(*(__nv_bfloat162*)&u0.y);
            float2 a1 = __bfloat1622float2(*(__nv_bfloat162*)&u1.x);
            float2 b1 = __bfloat1622float2(*(__nv_bfloat162*)&u1.y);
            float2 a2 = __bfloat1622float2(*(__nv_bfloat162*)&u2.x);
            float2 b2 = __bfloat1622float2(*(__nv_bfloat162*)&u2.y);
            float2 a3 = __bfloat1622float2(*(__nv_bfloat162*)&u3.x);
            float2 b3 = __bfloat1622float2(*(__nv_bfloat162*)&u3.y);
            acc.x += (a0.x + a1.x) + (a2.x + a3.x);
            acc.y += (a0.y + a1.y) + (a2.y + a3.y);
            acc.z += (b0.x + b1.x) + (b2.x + b3.x);
            acc.w += (b0.y + b1.y) + (b2.y + b3.y);
        }
        for (; j < cnt; j++) {
            int s0 = __shfl_sync(0xffffffffu, s, j);
            uint2 u0 = *(const uint2*)&hin[(size_t)s0 * HIDDEN + fo];
            float2 a0 = __bfloat1622float2(*(__nv_bfloat162*)&u0.x);
            float2 b0 = __bfloat1622float2(*(__nv_bfloat162*)&u0.y);
            acc.x += a0.x; acc.y += a0.y; acc.z += b0.x; acc.w += b0.y;
        }
    }
    float dd = d_dis[warp];
    acc.x *= dd; acc.y *= dd; acc.z *= dd; acc.w *= dd;
    *(float4*)&gout[(size_t)warp * HIDDEN + fo] = acc;
}

// ---------------- HMMA GEMM: 64-row tile, 2-pass A-split (A_hi+A_lo) x W_hi ----------------
// mode=0: hout(bf16) = relu(G@W+b)*dis   |   mode=1: fused segment-max pooling
#define OFF_BIAS 0
#define OFF_AHI  1024
#define OFF_ALO  (1024 + 16384)
#define OFF_BHI  (1024 + 32768)
#define GEMM_MMA_SMEM (1024 + 32768 + 32768)

__global__ __launch_bounds__(256, 2)
void k_gemm_mma(const float* __restrict__ G, int wsel,
                const float* __restrict__ bias,
                __nv_bfloat16* __restrict__ hout,
                const int* __restrict__ batch, int mode) {
    extern __shared__ char smem[];
    uint32_t sbase = smem_u32(smem);
    float* sbias = (float*)(smem + OFF_BIAS);
    int tid = threadIdx.x, lane = tid & 31, wid = tid >> 5;
    int row0 = blockIdx.x * 64;

    if (tid < HIDDEN) sbias[tid] = bias[tid];

    // stage B: W^T hi [128 n][256B], swizzled
    {
        const uint4* bh = (const uint4*)&d_wthi[wsel][0];
        #pragma unroll
        for (int i = 0; i < 8; i++) {
            int v = tid + 256 * i;
            int n = v >> 4, c16 = v & 15;
            uint32_t off = SWZ(n, c16 * 16);
            *(uint4*)(smem + OFF_BHI + off) = bh[v];
        }
    }
    // stage A: 64 rows of fp32 G -> bf16 hi/lo, swizzled
    {
        const float4* G4 = (const float4*)G;
        #pragma unroll
        for (int i = 0; i < 4; i++) {
            int v = tid + 256 * i;
            int r = v >> 4, c16 = v & 15;
            int row = row0 + r;
            float f[8] = {0.f, 0.f, 0.f, 0.f, 0.f, 0.f, 0.f, 0.f};
            if (row < N_NODES) {
                float4 q0 = G4[(size_t)row * 32 + c16 * 2];
                float4 q1 = G4[(size_t)row * 32 + c16 * 2 + 1];
                f[0] = q0.x; f[1] = q0.y; f[2] = q0.z; f[3] = q0.w;
                f[4] = q1.x; f[5] = q1.y; f[6] = q1.z; f[7] = q1.w;
            }
            __nv_bfloat162 hi[4], lo[4];
            #pragma unroll
            for (int j = 0; j < 4; j++) {
                __nv_bfloat16 h0 = __float2bfloat16(f[2 * j]);
                __nv_bfloat16 h1 = __float2bfloat16(f[2 * j + 1]);
                hi[j] = __nv_bfloat162(h0, h1);
                lo[j] = __floats2bfloat162_rn(f[2 * j] - __bfloat162float(h0),
                                              f[2 * j + 1] - __bfloat162float(h1));
            }
            uint32_t off = SWZ(r, c16 * 16);
            *(uint4*)(smem + OFF_AHI + off) = *(uint4*)hi;
            *(uint4*)(smem + OFF_ALO + off) = *(uint4*)lo;
        }
    }
    __syncthreads();

    int mi = wid >> 1;          // m-tile 0..3
    int nb = (wid & 1) * 64;    // n-half

    int a_row = mi * 16 + (lane & 7) + ((lane >> 3) & 1) * 8;
    int a_kx  = ((lane >> 4) & 1) * 16;
    uint32_t a_base = sbase + (uint32_t)(a_row * 256);
    int a_swz = (a_row & 7) << 4;

    int b_row = nb + (lane & 7) + ((lane & 16) ? 8 : 0);
    int b_kx  = (lane & 8) ? 16 : 0;
    int b_swz = (b_row & 7) << 4;

    float acc[8][4];
    #pragma unroll
    for (int nt = 0; nt < 8; nt++)
        #pragma unroll
        for (int j = 0; j < 4; j++) acc[nt][j] = 0.f;

    const uint32_t a_offs[2] = {OFF_AHI, OFF_ALO};

    #pragma unroll
    for (int p = 0; p < 2; p++) {
        uint32_t abase = a_base + a_offs[p];
        #pragma unroll
        for (int ks = 0; ks < 8; ks++) {
            int kb = ks * 32;
            uint32_t a0r, a1r, a2r, a3r;
            LDMATRIX_X4(a0r, a1r, a2r, a3r, abase + (uint32_t)((kb + a_kx) ^ a_swz));
            uint32_t b[16];
            #pragma unroll
            for (int j = 0; j < 4; j++) {
                uint32_t addr = sbase + OFF_BHI + (uint32_t)((b_row + j * 16) * 256)
                              + (uint32_t)((kb + b_kx) ^ b_swz);
                LDMATRIX_X4(b[4 * j], b[4 * j + 1], b[4 * j + 2], b[4 * j + 3], addr);
            }
            #pragma unroll
            for (int nt = 0; nt < 8; nt++)
                MMA_BF16(acc[nt][0], acc[nt][1], acc[nt][2], acc[nt][3],
                         a0r, a1r, a2r, a3r, b[2 * nt], b[2 * nt + 1]);
        }
    }

    int q = lane & 3, rq = lane >> 2;
    int rA = mi * 16 + rq;          // local rows
    int rB = rA + 8;
    int rowA = row0 + rA;
    int rowB = row0 + rB;

    if (mode == 0) {
        float scA = (rowA < N_NODES) ? d_dis[rowA] : 1.f;
        float scB = (rowB < N_NODES) ? d_dis[rowB] : 1.f;
        #pragma unroll
        for (int nt = 0; nt < 8; nt++) {
            int col = nb + nt * 8 + 2 * q;
            float bc0 = sbias[col], bc1 = sbias[col + 1];
            if (rowA < N_NODES) {
                __nv_bfloat162 v = __floats2bfloat162_rn(fmaxf(acc[nt][0] + bc0, 0.f) * scA,
                                                         fmaxf(acc[nt][1] + bc1, 0.f) * scA);
                *(uint32_t*)&hout[(size_t)rowA * HIDDEN + col] = *(uint32_t*)&v;
            }
            if (rowB < N_NODES) {
                __nv_bfloat162 v = __floats2bfloat162_rn(fmaxf(acc[nt][2] + bc0, 0.f) * scB,
                                                         fmaxf(acc[nt][3] + bc1, 0.f) * scB);
                *(uint32_t*)&hout[(size_t)rowB * HIDDEN + col] = *(uint32_t*)&v;
            }
        }
    } else {
        // fused pooling: stage relu values into smem, run-length segment-max + atomicMax
        __syncthreads();
        float* spool = (float*)(smem + OFF_AHI);     // [64][128] fp32 = 32 KB
        int* sbatch = (int*)(smem + OFF_BHI);        // 64 ints
        #pragma unroll
        for (int nt = 0; nt < 8; nt++) {
            int col = nb + nt * 8 + 2 * q;
            float bc0 = sbias[col], bc1 = sbias[col + 1];
            spool[rA * HIDDEN + col]     = fmaxf(acc[nt][0] + bc0, 0.f);
            spool[rA * HIDDEN + col + 1] = fmaxf(acc[nt][1] + bc1, 0.f);
            spool[rB * HIDDEN + col]     = fmaxf(acc[nt][2] + bc0, 0.f);
            spool[rB * HIDDEN + col + 1] = fmaxf(acc[nt][3] + bc1, 0.f);
        }
        if (tid < 64 && row0 + tid < N_NODES) sbatch[tid] = batch[row0 + tid];
        __syncthreads();
        if (tid < HIDDEN) {
            int cur = -1; float run = 0.f;
            #pragma unroll 4
            for (int r = 0; r < 64; r++) {
                if (row0 + r >= N_NODES) break;
                int g = sbatch[r];
                float v = spool[r * HIDDEN + tid];
                if (g != cur) {
                    if (cur >= 0)
                        atomicMax((int*)&d_pool[cur * HIDDEN + tid], __float_as_int(run));
                    cur = g; run = v;
                } else {
                    run = fmaxf(run, v);
                }
            }
            if (cur >= 0)
                atomicMax((int*)&d_pool[cur * HIDDEN + tid], __float_as_int(run));
        }
    }
}

// ---------------- final: warp-per-graph, out[512,2] = pooled @ Wl + bl ----------------
__global__ void k_final(const float* __restrict__ Wl, const float* __restrict__ bl,
                        float* __restrict__ out) {
    __shared__ float sW[HIDDEN * 2];
    __shared__ float sb[2];
    int tid = threadIdx.x;
    if (tid < HIDDEN * 2) sW[tid] = Wl[tid];
    if (tid < 2) sb[tid] = bl[tid];
    __syncthreads();

    int g = (blockIdx.x * 256 + tid) >> 5;    // graph id
    int lane = tid & 31;
    if (g >= N_GRAPHS) return;

    float4 p = *(const float4*)&d_pool[g * HIDDEN + lane * 4];
    int k0 = lane * 4;
    float a0 = p.x * sW[k0 * 2]     + p.y * sW[(k0 + 1) * 2]
             + p.z * sW[(k0 + 2) * 2] + p.w * sW[(k0 + 3) * 2];
    float a1 = p.x * sW[k0 * 2 + 1]     + p.y * sW[(k0 + 1) * 2 + 1]
             + p.z * sW[(k0 + 2) * 2 + 1] + p.w * sW[(k0 + 3) * 2 + 1];
    #pragma unroll
    for (int o = 16; o > 0; o >>= 1) {
        a0 += __shfl_xor_sync(0xffffffffu, a0, o);
        a1 += __shfl_xor_sync(0xffffffffu, a1, o);
    }
    if (lane == 0) {
        out[g * 2 + 0] = a0 + sb[0];
        out[g * 2 + 1] = a1 + sb[1];
    }
}

// ---------------- launcher ----------------
extern "C" void kernel_launch(void* const* d_in, const int* in_sizes, int n_in,
                              void* d_out, int out_size) {
    const float* x     = (const float*)d_in[0];
    const int*   ei    = (const int*)  d_in[1];
    const int*   batch = (const int*)  d_in[2];
    const float* W1 = (const float*)d_in[3];
    const float* b1 = (const float*)d_in[4];
    const float* W2 = (const float*)d_in[5];
    const float* b2 = (const float*)d_in[6];
    const float* W3 = (const float*)d_in[7];
    const float* b3 = (const float*)d_in[8];
    const float* Wl = (const float*)d_in[9];
    const float* bl = (const float*)d_in[10];
    float* out = (float*)d_out;

    const int* src = ei;
    const int* dst = ei + N_EDGES;

    __nv_bfloat16* h1; cudaGetSymbolAddress((void**)&h1, d_h1);
    __nv_bfloat16* h2; cudaGetSymbolAddress((void**)&h2, d_h2);
    float* agg;  cudaGetSymbolAddress((void**)&agg, d_agg);

    cudaFuncSetAttribute(k_gemm_mma, cudaFuncAttributeMaxDynamicSharedMemorySize, GEMM_MMA_SMEM);

    const int TPB = 256;

    k_prep_w      <<<dim3(128, 2), 128>>>(W2, W3);   // also zeroes d_deg / d_pool
    k_degree      <<<(N_EDGES / 4 + TPB - 1) / TPB, TPB>>>(dst);
    k_dis_scanpart<<<SCAN_BLOCKS, 1024>>>(x);
    k_scan_finish <<<SCAN_BLOCKS, 1024>>>();
    k_fill_edges  <<<(N_EDGES + TPB - 1) / TPB, TPB>>>(src, dst);

    // layer 1 -> h1 (bf16, dis-prescaled)
    k_layer1<<<(N_NODES * 32 + TPB - 1) / TPB, TPB>>>(W1, b1);

    // layer 2: agg = A h1 ; h2 = bf16(relu(agg W2 + b2) * dis)
    k_aggregate<<<(N_NODES * 32 + TPB - 1) / TPB, TPB>>>(h1, agg);
    k_gemm_mma<<<(N_NODES + 63) / 64, 256, GEMM_MMA_SMEM>>>(agg, 0, b2, h2, batch, 0);

    // layer 3: agg = A h2 ; fused GEMM + segment-max pooling
    k_aggregate<<<(N_NODES * 32 + TPB - 1) / TPB, TPB>>>(h2, agg);
    k_gemm_mma<<<(N_NODES + 63) / 64, 256, GEMM_MMA_SMEM>>>(agg, 1, b3, nullptr, batch, 1);

    k_final<<<(N_GRAPHS * 32 + TPB - 1) / TPB, TPB>>>(Wl, bl, out);
}

// round 15
// speedup vs baseline: 1.2387x; 1.0095x over previous
#include <cuda_runtime.h>
#include <cuda_bf16.h>
#include <cstdint>

#define N_NODES  100000
#define N_EDGES  1600000
#define HIDDEN   128
#define IN_FEAT  7
#define N_GRAPHS 512
#define N_TOTAL_E (N_EDGES + N_NODES)
#define SCAN_BLOCKS ((N_NODES + 1023) / 1024)   // 98

// ---------------- scratch ----------------
__device__ int   d_deg[N_NODES];
__device__ float d_dis[N_NODES];
__device__ float d_xs[(size_t)N_NODES * 8];     // padded to 8 floats/row (32B aligned)
__device__ int   d_rowptr[N_NODES + 1];
__device__ int   d_bsum[SCAN_BLOCKS];
__device__ int   d_slot[N_EDGES];               // per-edge slot within its dst list
__device__ int   d_csr_src[N_TOTAL_E];
__device__ __nv_bfloat16 d_h1[(size_t)N_NODES * HIDDEN];
__device__ __nv_bfloat16 d_h2[(size_t)N_NODES * HIDDEN];
__device__ float d_agg[(size_t)N_NODES * HIDDEN];
__device__ float d_pool[N_GRAPHS * HIDDEN];
__device__ __nv_bfloat16 d_wthi[2][HIDDEN * HIDDEN];   // W^T hi (bf16), [n][k]

// ---------------- helpers ----------------
__device__ __forceinline__ uint32_t smem_u32(const void* p) {
    uint32_t a;
    asm("{ .reg .u64 t; cvta.to.shared.u64 t, %1; cvt.u32.u64 %0, t; }" : "=r"(a) : "l"(p));
    return a;
}

// XOR-16B swizzled byte offset inside a [rows][256B] bf16 tile
#define SWZ(row, kb) ((uint32_t)((row) * 256 + ((kb) ^ (((row) & 7) << 4))))

#define LDMATRIX_X4(r0, r1, r2, r3, addr) \
    asm volatile("ldmatrix.sync.aligned.m8n8.x4.shared.b16 {%0,%1,%2,%3}, [%4];" \
        : "=r"(r0), "=r"(r1), "=r"(r2), "=r"(r3) : "r"(addr))

#define MMA_BF16(c0, c1, c2, c3, a0, a1, a2, a3, b0, b1) \
    asm volatile("mma.sync.aligned.m16n8k16.row.col.f32.bf16.bf16.f32 " \
        "{%0,%1,%2,%3}, {%4,%5,%6,%7}, {%8,%9}, {%0,%1,%2,%3};" \
        : "+f"(c0), "+f"(c1), "+f"(c2), "+f"(c3) \
        : "r"(a0), "r"(a1), "r"(a2), "r"(a3), "r"(b0), "r"(b1))

// ---------------- setup ----------------
// degree count; atomic return value IS the edge's slot within its dst list
__global__ void k_degree(const int* __restrict__ dst) {
    int i = blockIdx.x * blockDim.x + threadIdx.x;
    int base = i * 4;
    if (base + 3 < N_EDGES) {
        int4 d4 = *(const int4*)&dst[base];
        int4 s4;
        s4.x = atomicAdd(&d_deg[d4.x], 1);
        s4.y = atomicAdd(&d_deg[d4.y], 1);
        s4.z = atomicAdd(&d_deg[d4.z], 1);
        s4.w = atomicAdd(&d_deg[d4.w], 1);
        *(int4*)&d_slot[base] = s4;
    } else {
        for (int e = base; e < N_EDGES; e++) d_slot[e] = atomicAdd(&d_deg[dst[e]], 1);
    }
}

__global__ void k_dis_scanpart(const float* __restrict__ x) {
    __shared__ int wsum[32];
    int tid = threadIdx.x, lane = tid & 31, wid = tid >> 5;
    int i = blockIdx.x * 1024 + tid;
    int v = 0;
    if (i < N_NODES) {
        v = d_deg[i] + 1;
        float d = rsqrtf((float)v);
        d_dis[i] = d;
        float4 q0, q1;
        q0.x = d * x[(size_t)i * IN_FEAT + 0];
        q0.y = d * x[(size_t)i * IN_FEAT + 1];
        q0.z = d * x[(size_t)i * IN_FEAT + 2];
        q0.w = d * x[(size_t)i * IN_FEAT + 3];
        q1.x = d * x[(size_t)i * IN_FEAT + 4];
        q1.y = d * x[(size_t)i * IN_FEAT + 5];
        q1.z = d * x[(size_t)i * IN_FEAT + 6];
        q1.w = 0.f;
        *(float4*)&d_xs[(size_t)i * 8]     = q0;
        *(float4*)&d_xs[(size_t)i * 8 + 4] = q1;
    }
    int xx = v;
    #pragma unroll
    for (int o = 1; o < 32; o <<= 1) {
        int y = __shfl_up_sync(0xffffffffu, xx, o);
        if (lane >= o) xx += y;
    }
    if (lane == 31) wsum[wid] = xx;
    __syncthreads();
    if (wid == 0) {
        int s = wsum[lane];
        #pragma unroll
        for (int o = 1; o < 32; o <<= 1) {
            int y = __shfl_up_sync(0xffffffffu, s, o);
            if (lane >= o) s += y;
        }
        wsum[lane] = s;
    }
    __syncthreads();
    int excl = (wid > 0 ? wsum[wid - 1] : 0) + xx - v;
    if (i < N_NODES) d_rowptr[i] = excl;
    if (tid == 1023) d_bsum[blockIdx.x] = wsum[31];
}

__global__ void k_scan_finish() {
    __shared__ int soff;
    if (threadIdx.x == 0) {
        int a = 0;
        for (int k = 0; k < blockIdx.x; k++) a += d_bsum[k];
        soff = a;
    }
    __syncthreads();
    int i = blockIdx.x * 1024 + threadIdx.x;
    if (i < N_NODES) {
        int rp = d_rowptr[i] + soff;
        d_rowptr[i] = rp;
        d_csr_src[rp] = i;          // self-loop at slot 0
    }
    if (blockIdx.x == 0 && threadIdx.x == 0) d_rowptr[N_NODES] = N_TOTAL_E;
}

// atomic-free CSR fill using precomputed slots
__global__ void k_fill_edges(const int* __restrict__ src, const int* __restrict__ dst) {
    int i = blockIdx.x * blockDim.x + threadIdx.x;
    if (i < N_EDGES) {
        int d = dst[i];
        d_csr_src[d_rowptr[d] + 1 + d_slot[i]] = src[i];
    }
}

// W^T bf16 precompute + zero-init of deg/pool: grid (128, 2), block 128
__global__ void k_prep_w(const float* __restrict__ W2, const float* __restrict__ W3) {
    int n = blockIdx.x, k = threadIdx.x, L = blockIdx.y;
    const float* W = (L == 0) ? W2 : W3;
    d_wthi[L][n * HIDDEN + k] = __float2bfloat16(W[k * HIDDEN + n]);
    int gt = (L * 128 + n) * 128 + k;          // 0..32767
    #pragma unroll
    for (int r = 0; r < 2; r++) {
        int p = gt + r * 32768;
        if (p < N_GRAPHS * HIDDEN) d_pool[p] = 0.f;
    }
    #pragma unroll
    for (int r = 0; r < 4; r++) {
        int p = gt + r * 32768;
        if (p < N_NODES) d_deg[p] = 0;
    }
}

// ---------------- layer 1: lane-per-edge gather + warp reduce + 7->128 GEMM ----------------
__global__ void k_layer1(const float* __restrict__ W1, const float* __restrict__ b1) {
    __shared__ float sW[IN_FEAT * HIDDEN];
    __shared__ float sb[HIDDEN];
    int tid = threadIdx.x;
    for (int i = tid; i < IN_FEAT * HIDDEN; i += 256) sW[i] = W1[i];
    if (tid < HIDDEN) sb[tid] = b1[tid];
    __syncthreads();

    int warp = (blockIdx.x * 256 + tid) >> 5;
    int lane = tid & 31;
    if (warp >= N_NODES) return;

    int beg = d_rowptr[warp], end = d_rowptr[warp + 1];
    float a[8];
    #pragma unroll
    for (int j = 0; j < 8; j++) a[j] = 0.f;

    for (int e = beg + lane; e < end; e += 32) {
        int s = d_csr_src[e];
        float4 q0 = *(const float4*)&d_xs[(size_t)s * 8];
        float4 q1 = *(const float4*)&d_xs[(size_t)s * 8 + 4];
        a[0] += q0.x; a[1] += q0.y; a[2] += q0.z; a[3] += q0.w;
        a[4] += q1.x; a[5] += q1.y; a[6] += q1.z; a[7] += q1.w;
    }
    #pragma unroll
    for (int o = 16; o > 0; o >>= 1) {
        #pragma unroll
        for (int j = 0; j < IN_FEAT; j++)
            a[j] += __shfl_xor_sync(0xffffffffu, a[j], o);
    }

    float dd = d_dis[warp];
    #pragma unroll
    for (int j = 0; j < IN_FEAT; j++) a[j] *= dd;

    int c0 = lane * 4;
    float4 o;
    o.x = sb[c0]; o.y = sb[c0 + 1]; o.z = sb[c0 + 2]; o.w = sb[c0 + 3];
    #pragma unroll
    for (int j = 0; j < IN_FEAT; j++) {
        o.x += a[j] * sW[j * HIDDEN + c0];
        o.y += a[j] * sW[j * HIDDEN + c0 + 1];
        o.z += a[j] * sW[j * HIDDEN + c0 + 2];
        o.w += a[j] * sW[j * HIDDEN + c0 + 3];
    }
    o.x = fmaxf(o.x, 0.f) * dd; o.y = fmaxf(o.y, 0.f) * dd;
    o.z = fmaxf(o.z, 0.f) * dd; o.w = fmaxf(o.w, 0.f) * dd;
    __nv_bfloat162 p[2];
    p[0] = __floats2bfloat162_rn(o.x, o.y);
    p[1] = __floats2bfloat162_rn(o.z, o.w);
    *(uint2*)&d_h1[(size_t)warp * HIDDEN + c0] = *(uint2*)p;
}

// ---------------- aggregation (bf16 in, fp32 out) ----------------
__global__ void k_aggregate(const __nv_bfloat16* __restrict__ hin, float* __restrict__ gout) {
    int warp = (blockIdx.x * blockDim.x + threadIdx.x) >> 5;
    int lane = threadIdx.x & 31;
    if (warp >= N_NODES) return;
    int beg = d_rowptr[warp], end = d_rowptr[warp + 1];
    float4 acc = make_float4(0.f, 0.f, 0.f, 0.f);
    int fo = lane * 4;
    for (int e0 = beg; e0 < end; e0 += 32) {
        int e = e0 + lane;
        int s = (e < end) ? d_csr_src[e] : 0;
        int cnt = min(32, end - e0);
        int j = 0;
        for (; j + 3 < cnt; j += 4) {
            int s0 = __shfl_sync(0xffffffffu, s, j);
            int s1 = __shfl_sync(0xffffffffu, s, j + 1);
            int s2 = __shfl_sync(0xffffffffu, s, j + 2);
            int s3 = __shfl_sync(0xffffffffu, s, j + 3);
            uint2 u0 = *(const uint2*)&hin[(size_t)s0 * HIDDEN + fo];
            uint2 u1 = *(const uint2*)&hin[(size_t)s1 * HIDDEN + fo];
            uint2 u2 = *(const uint2*)&hin[(size_t)s2 * HIDDEN + fo];
            uint2 u3 = *(const uint2*)&hin[(size_t)s3 * HIDDEN + fo];
            float2 a0 = __bfloat1622float2(*(__nv_bfloat162*)&u0.x);
            float2 b0 = __bfloat1622float2(*(__nv_bfloat162*)&u0.y);
            float2 a1 = __bfloat1622float2(*(__nv_bfloat162*)&u1.x);
            float2 b1 = __bfloat1622float2(*(__nv_bfloat162*)&u1.y);
            float2 a2 = __bfloat1622float2(*(__nv_bfloat162*)&u2.x);
            float2 b2 = __bfloat1622float2(*(__nv_bfloat162*)&u2.y);
            float2 a3 = __bfloat1622float2(*(__nv_bfloat162*)&u3.x);
            float2 b3 = __bfloat1622float2(*(__nv_bfloat162*)&u3.y);
            acc.x += (a0.x + a1.x) + (a2.x + a3.x);
            acc.y += (a0.y + a1.y) + (a2.y + a3.y);
            acc.z += (b0.x + b1.x) + (b2.x + b3.x);
            acc.w += (b0.y + b1.y) + (b2.y + b3.y);
        }
        for (; j < cnt; j++) {
            int s0 = __shfl_sync(0xffffffffu, s, j);
            uint2 u0 = *(const uint2*)&hin[(size_t)s0 * HIDDEN + fo];
            float2 a0 = __bfloat1622float2(*(__nv_bfloat162*)&u0.x);
            float2 b0 = __bfloat1622float2(*(__nv_bfloat162*)&u0.y);
            acc.x += a0.x; acc.y += a0.y; acc.z += b0.x; acc.w += b0.y;
        }
    }
    float dd = d_dis[warp];
    acc.x *= dd; acc.y *= dd; acc.z *= dd; acc.w *= dd;
    *(float4*)&gout[(size_t)warp * HIDDEN + fo] = acc;
}

// ---------------- HMMA GEMM: 64-row tile, 2-pass A-split (A_hi+A_lo) x W_hi ----------------
// mode=0: hout(bf16) = relu(G@W+b)*dis   |   mode=1: fused segment-max pooling
#define OFF_BIAS 0
#define OFF_AHI  1024
#define OFF_ALO  (1024 + 16384)
#define OFF_BHI  (1024 + 32768)
#define GEMM_MMA_SMEM (1024 + 32768 + 32768)

__global__ __launch_bounds__(256, 2)
void k_gemm_mma(const float* __restrict__ G, int wsel,
                const float* __restrict__ bias,
                __nv_bfloat16* __restrict__ hout,
                const int* __restrict__ batch, int mode) {
    extern __shared__ char smem[];
    uint32_t sbase = smem_u32(smem);
    float* sbias = (float*)(smem + OFF_BIAS);
    int tid = threadIdx.x, lane = tid & 31, wid = tid >> 5;
    int row0 = blockIdx.x * 64;

    if (tid < HIDDEN) sbias[tid] = bias[tid];

    // stage B: W^T hi [128 n][256B], swizzled
    {
        const uint4* bh = (const uint4*)&d_wthi[wsel][0];
        #pragma unroll
        for (int i = 0; i < 8; i++) {
            int v = tid + 256 * i;
            int n = v >> 4, c16 = v & 15;
            uint32_t off = SWZ(n, c16 * 16);
            *(uint4*)(smem + OFF_BHI + off) = bh[v];
        }
    }
    // stage A: 64 rows of fp32 G -> bf16 hi/lo, swizzled
    {
        const float4* G4 = (const float4*)G;
        #pragma unroll
        for (int i = 0; i < 4; i++) {
            int v = tid + 256 * i;
            int r = v >> 4, c16 = v & 15;
            int row = row0 + r;
            float f[8] = {0.f, 0.f, 0.f, 0.f, 0.f, 0.f, 0.f, 0.f};
            if (row < N_NODES) {
                float4 q0 = G4[(size_t)row * 32 + c16 * 2];
                float4 q1 = G4[(size_t)row * 32 + c16 * 2 + 1];
                f[0] = q0.x; f[1] = q0.y; f[2] = q0.z; f[3] = q0.w;
                f[4] = q1.x; f[5] = q1.y; f[6] = q1.z; f[7] = q1.w;
            }
            __nv_bfloat162 hi[4], lo[4];
            #pragma unroll
            for (int j = 0; j < 4; j++) {
                __nv_bfloat16 h0 = __float2bfloat16(f[2 * j]);
                __nv_bfloat16 h1 = __float2bfloat16(f[2 * j + 1]);
                hi[j] = __nv_bfloat162(h0, h1);
                lo[j] = __floats2bfloat162_rn(f[2 * j] - __bfloat162float(h0),
                                              f[2 * j + 1] - __bfloat162float(h1));
            }
            uint32_t off = SWZ(r, c16 * 16);
            *(uint4*)(smem + OFF_AHI + off) = *(uint4*)hi;
            *(uint4*)(smem + OFF_ALO + off) = *(uint4*)lo;
        }
    }
    __syncthreads();

    int mi = wid >> 1;          // m-tile 0..3
    int nb = (wid & 1) * 64;    // n-half

    int a_row = mi * 16 + (lane & 7) + ((lane >> 3) & 1) * 8;
    int a_kx  = ((lane >> 4) & 1) * 16;
    uint32_t a_base = sbase + (uint32_t)(a_row * 256);
    int a_swz = (a_row & 7) << 4;

    int b_row = nb + (lane & 7) + ((lane & 16) ? 8 : 0);
    int b_kx  = (lane & 8) ? 16 : 0;
    int b_swz = (b_row & 7) << 4;

    float acc[8][4];
    #pragma unroll
    for (int nt = 0; nt < 8; nt++)
        #pragma unroll
        for (int j = 0; j < 4; j++) acc[nt][j] = 0.f;

    const uint32_t a_offs[2] = {OFF_AHI, OFF_ALO};

    #pragma unroll
    for (int p = 0; p < 2; p++) {
        uint32_t abase = a_base + a_offs[p];
        #pragma unroll
        for (int ks = 0; ks < 8; ks++) {
            int kb = ks * 32;
            uint32_t a0r, a1r, a2r, a3r;
            LDMATRIX_X4(a0r, a1r, a2r, a3r, abase + (uint32_t)((kb + a_kx) ^ a_swz));
            uint32_t b[16];
            #pragma unroll
            for (int j = 0; j < 4; j++) {
                uint32_t addr = sbase + OFF_BHI + (uint32_t)((b_row + j * 16) * 256)
                              + (uint32_t)((kb + b_kx) ^ b_swz);
                LDMATRIX_X4(b[4 * j], b[4 * j + 1], b[4 * j + 2], b[4 * j + 3], addr);
            }
            #pragma unroll
            for (int nt = 0; nt < 8; nt++)
                MMA_BF16(acc[nt][0], acc[nt][1], acc[nt][2], acc[nt][3],
                         a0r, a1r, a2r, a3r, b[2 * nt], b[2 * nt + 1]);
        }
    }

    int q = lane & 3, rq = lane >> 2;
    int rA = mi * 16 + rq;          // local rows
    int rB = rA + 8;
    int rowA = row0 + rA;
    int rowB = row0 + rB;

    if (mode == 0) {
        float scA = (rowA < N_NODES) ? d_dis[rowA] : 1.f;
        float scB = (rowB < N_NODES) ? d_dis[rowB] : 1.f;
        #pragma unroll
        for (int nt = 0; nt < 8; nt++) {
            int col = nb + nt * 8 + 2 * q;
            float bc0 = sbias[col], bc1 = sbias[col + 1];
            if (rowA < N_NODES) {
                __nv_bfloat162 v = __floats2bfloat162_rn(fmaxf(acc[nt][0] + bc0, 0.f) * scA,
                                                         fmaxf(acc[nt][1] + bc1, 0.f) * scA);
                *(uint32_t*)&hout[(size_t)rowA * HIDDEN + col] = *(uint32_t*)&v;
            }
            if (rowB < N_NODES) {
                __nv_bfloat162 v = __floats2bfloat162_rn(fmaxf(acc[nt][2] + bc0, 0.f) * scB,
                                                         fmaxf(acc[nt][3] + bc1, 0.f) * scB);
                *(uint32_t*)&hout[(size_t)rowB * HIDDEN + col] = *(uint32_t*)&v;
            }
        }
    } else {
        // fused pooling: stage relu values into smem, run-length segment-max + atomicMax
        __syncthreads();
        float* spool = (float*)(smem + OFF_AHI);     // [64][128] fp32 = 32 KB
        int* sbatch = (int*)(smem + OFF_BHI);        // 64 ints
        #pragma unroll
        for (int nt = 0; nt < 8; nt++) {
            int col = nb + nt * 8 + 2 * q;
            float bc0 = sbias[col], bc1 = sbias[col + 1];
            spool[rA * HIDDEN + col]     = fmaxf(acc[nt][0] + bc0, 0.f);
            spool[rA * HIDDEN + col + 1] = fmaxf(acc[nt][1] + bc1, 0.f);
            spool[rB * HIDDEN + col]     = fmaxf(acc[nt][2] + bc0, 0.f);
            spool[rB * HIDDEN + col + 1] = fmaxf(acc[nt][3] + bc1, 0.f);
        }
        if (tid < 64 && row0 + tid < N_NODES) sbatch[tid] = batch[row0 + tid];
        __syncthreads();
        if (tid < HIDDEN) {
            int cur = -1; float run = 0.f;
            #pragma unroll 4
            for (int r = 0; r < 64; r++) {
                if (row0 + r >= N_NODES) break;
                int g = sbatch[r];
                float v = spool[r * HIDDEN + tid];
                if (g != cur) {
                    if (cur >= 0)
                        atomicMax((int*)&d_pool[cur * HIDDEN + tid], __float_as_int(run));
                    cur = g; run = v;
                } else {
                    run = fmaxf(run, v);
                }
            }
            if (cur >= 0)
                atomicMax((int*)&d_pool[cur * HIDDEN + tid], __float_as_int(run));
        }
    }
}

// ---------------- final: warp-per-graph, out[512,2] = pooled @ Wl + bl ----------------
__global__ void k_final(const float* __restrict__ Wl, const float* __restrict__ bl,
                        float* __restrict__ out) {
    __shared__ float sW[HIDDEN * 2];
    __shared__ float sb[2];
    int tid = threadIdx.x;
    if (tid < HIDDEN * 2) sW[tid] = Wl[tid];
    if (tid < 2) sb[tid] = bl[tid];
    __syncthreads();

    int g = (blockIdx.x * 256 + tid) >> 5;    // graph id
    int lane = tid & 31;
    if (g >= N_GRAPHS) return;

    float4 p = *(const float4*)&d_pool[g * HIDDEN + lane * 4];
    int k0 = lane * 4;
    float a0 = p.x * sW[k0 * 2]     + p.y * sW[(k0 + 1) * 2]
             + p.z * sW[(k0 + 2) * 2] + p.w * sW[(k0 + 3) * 2];
    float a1 = p.x * sW[k0 * 2 + 1]     + p.y * sW[(k0 + 1) * 2 + 1]
             + p.z * sW[(k0 + 2) * 2 + 1] + p.w * sW[(k0 + 3) * 2 + 1];
    #pragma unroll
    for (int o = 16; o > 0; o >>= 1) {
        a0 += __shfl_xor_sync(0xffffffffu, a0, o);
        a1 += __shfl_xor_sync(0xffffffffu, a1, o);
    }
    if (lane == 0) {
        out[g * 2 + 0] = a0 + sb[0];
        out[g * 2 + 1] = a1 + sb[1];
    }
}

// ---------------- launcher ----------------
extern "C" void kernel_launch(void* const* d_in, const int* in_sizes, int n_in,
                              void* d_out, int out_size) {
    const float* x     = (const float*)d_in[0];
    const int*   ei    = (const int*)  d_in[1];
    const int*   batch = (const int*)  d_in[2];
    const float* W1 = (const float*)d_in[3];
    const float* b1 = (const float*)d_in[4];
    const float* W2 = (const float*)d_in[5];
    const float* b2 = (const float*)d_in[6];
    const float* W3 = (const float*)d_in[7];
    const float* b3 = (const float*)d_in[8];
    const float* Wl = (const float*)d_in[9];
    const float* bl = (const float*)d_in[10];
    float* out = (float*)d_out;

    const int* src = ei;
    const int* dst = ei + N_EDGES;

    __nv_bfloat16* h1; cudaGetSymbolAddress((void**)&h1, d_h1);
    __nv_bfloat16* h2; cudaGetSymbolAddress((void**)&h2, d_h2);
    float* agg;  cudaGetSymbolAddress((void**)&agg, d_agg);

    cudaFuncSetAttribute(k_gemm_mma, cudaFuncAttributeMaxDynamicSharedMemorySize, GEMM_MMA_SMEM);

    const int TPB = 256;

    k_prep_w      <<<dim3(128, 2), 128>>>(W2, W3);   // also zeroes d_deg / d_pool
    k_degree      <<<(N_EDGES / 4 + TPB - 1) / TPB, TPB>>>(dst);
    k_dis_scanpart<<<SCAN_BLOCKS, 1024>>>(x);
    k_scan_finish <<<SCAN_BLOCKS, 1024>>>();
    k_fill_edges  <<<(N_EDGES + TPB - 1) / TPB, TPB>>>(src, dst);

    // layer 1 -> h1 (bf16, dis-prescaled)
    k_layer1<<<(N_NODES * 32 + TPB - 1) / TPB, TPB>>>(W1, b1);

    // layer 2: agg = A h1 ; h2 = bf16(relu(agg W2 + b2) * dis)
    k_aggregate<<<(N_NODES * 32 + TPB - 1) / TPB, TPB>>>(h1, agg);
    k_gemm_mma<<<(N_NODES + 63) / 64, 256, GEMM_MMA_SMEM>>>(agg, 0, b2, h2, batch, 0);

    // layer 3: agg = A h2 ; fused GEMM + segment-max pooling
    k_aggregate<<<(N_NODES * 32 + TPB - 1) / TPB, TPB>>>(h2, agg);
    k_gemm_mma<<<(N_NODES + 63) / 64, 256, GEMM_MMA_SMEM>>>(agg, 1, b3, nullptr, batch, 1);

    k_final<<<(N_GRAPHS * 32 + TPB - 1) / TPB, TPB>>>(Wl, bl, out);
}

// round 17
// speedup vs baseline: 1.2488x; 1.0082x over previous
#include <cuda_runtime.h>
#include <cuda_bf16.h>
#include <cstdint>

#define N_NODES  100000
#define N_EDGES  1600000
#define HIDDEN   128
#define IN_FEAT  7
#define N_GRAPHS 512
#define N_TOTAL_E (N_EDGES + N_NODES)
#define SCAN_BLOCKS ((N_NODES + 1023) / 1024)   // 98

// ---------------- scratch ----------------
__device__ int   d_deg[N_NODES];
__device__ float d_dis[N_NODES];
__device__ float d_xs[(size_t)N_NODES * 8];     // padded to 8 floats/row (32B aligned)
__device__ int   d_rowptr[N_NODES + 1];
__device__ int   d_bsum[SCAN_BLOCKS];
__device__ int   d_slot[N_EDGES];               // per-edge slot within its dst list
__device__ int   d_csr_src[N_TOTAL_E];
__device__ __nv_bfloat16 d_h1[(size_t)N_NODES * HIDDEN];
__device__ __nv_bfloat16 d_h2[(size_t)N_NODES * HIDDEN];
__device__ float d_agg[(size_t)N_NODES * HIDDEN];
__device__ float d_pool[N_GRAPHS * HIDDEN];
__device__ __nv_bfloat16 d_wthi[2][HIDDEN * HIDDEN];   // W^T hi (bf16), [n][k]

// ---------------- helpers ----------------
__device__ __forceinline__ uint32_t smem_u32(const void* p) {
    uint32_t a;
    asm("{ .reg .u64 t; cvta.to.shared.u64 t, %1; cvt.u32.u64 %0, t; }" : "=r"(a) : "l"(p));
    return a;
}

// XOR-16B swizzled byte offset inside a [rows][256B] bf16 tile
#define SWZ(row, kb) ((uint32_t)((row) * 256 + ((kb) ^ (((row) & 7) << 4))))

#define LDMATRIX_X4(r0, r1, r2, r3, addr) \
    asm volatile("ldmatrix.sync.aligned.m8n8.x4.shared.b16 {%0,%1,%2,%3}, [%4];" \
        : "=r"(r0), "=r"(r1), "=r"(r2), "=r"(r3) : "r"(addr))

#define MMA_BF16(c0, c1, c2, c3, a0, a1, a2, a3, b0, b1) \
    asm volatile("mma.sync.aligned.m16n8k16.row.col.f32.bf16.bf16.f32 " \
        "{%0,%1,%2,%3}, {%4,%5,%6,%7}, {%8,%9}, {%0,%1,%2,%3};" \
        : "+f"(c0), "+f"(c1), "+f"(c2), "+f"(c3) \
        : "r"(a0), "r"(a1), "r"(a2), "r"(a3), "r"(b0), "r"(b1))

// ---------------- setup ----------------
// degree count; atomic return value IS the edge's slot within its dst list
__global__ void k_degree(const int* __restrict__ dst) {
    int i = blockIdx.x * blockDim.x + threadIdx.x;
    int base = i * 4;
    if (base + 3 < N_EDGES) {
        int4 d4 = *(const int4*)&dst[base];
        int4 s4;
        s4.x = atomicAdd(&d_deg[d4.x], 1);
        s4.y = atomicAdd(&d_deg[d4.y], 1);
        s4.z = atomicAdd(&d_deg[d4.z], 1);
        s4.w = atomicAdd(&d_deg[d4.w], 1);
        *(int4*)&d_slot[base] = s4;
    } else {
        for (int e = base; e < N_EDGES; e++) d_slot[e] = atomicAdd(&d_deg[dst[e]], 1);
    }
}

__global__ void k_dis_scanpart(const float* __restrict__ x) {
    __shared__ int wsum[32];
    int tid = threadIdx.x, lane = tid & 31, wid = tid >> 5;
    int i = blockIdx.x * 1024 + tid;
    int v = 0;
    if (i < N_NODES) {
        v = d_deg[i] + 1;
        float d = rsqrtf((float)v);
        d_dis[i] = d;
        float4 q0, q1;
        q0.x = d * x[(size_t)i * IN_FEAT + 0];
        q0.y = d * x[(size_t)i * IN_FEAT + 1];
        q0.z = d * x[(size_t)i * IN_FEAT + 2];
        q0.w = d * x[(size_t)i * IN_FEAT + 3];
        q1.x = d * x[(size_t)i * IN_FEAT + 4];
        q1.y = d * x[(size_t)i * IN_FEAT + 5];
        q1.z = d * x[(size_t)i * IN_FEAT + 6];
        q1.w = 0.f;
        *(float4*)&d_xs[(size_t)i * 8]     = q0;
        *(float4*)&d_xs[(size_t)i * 8 + 4] = q1;
    }
    int xx = v;
    #pragma unroll
    for (int o = 1; o < 32; o <<= 1) {
        int y = __shfl_up_sync(0xffffffffu, xx, o);
        if (lane >= o) xx += y;
    }
    if (lane == 31) wsum[wid] = xx;
    __syncthreads();
    if (wid == 0) {
        int s = wsum[lane];
        #pragma unroll
        for (int o = 1; o < 32; o <<= 1) {
            int y = __shfl_up_sync(0xffffffffu, s, o);
            if (lane >= o) s += y;
        }
        wsum[lane] = s;
    }
    __syncthreads();
    int excl = (wid > 0 ? wsum[wid - 1] : 0) + xx - v;
    if (i < N_NODES) d_rowptr[i] = excl;
    if (tid == 1023) d_bsum[blockIdx.x] = wsum[31];
}

__global__ void k_scan_finish() {
    __shared__ int soff;
    int tid = threadIdx.x;
    if (tid < 32) {
        int a = 0;
        for (int k = tid; k < blockIdx.x; k += 32) a += d_bsum[k];
        #pragma unroll
        for (int o = 16; o > 0; o >>= 1) a += __shfl_xor_sync(0xffffffffu, a, o);
        if (tid == 0) soff = a;
    }
    __syncthreads();
    int i = blockIdx.x * 1024 + tid;
    if (i < N_NODES) {
        int rp = d_rowptr[i] + soff;
        d_rowptr[i] = rp;
        d_csr_src[rp] = i;          // self-loop at slot 0
    }
    if (blockIdx.x == 0 && tid == 0) d_rowptr[N_NODES] = N_TOTAL_E;
}

// atomic-free CSR fill using precomputed slots
__global__ void k_fill_edges(const int* __restrict__ src, const int* __restrict__ dst) {
    int i = blockIdx.x * blockDim.x + threadIdx.x;
    if (i < N_EDGES) {
        int d = dst[i];
        d_csr_src[d_rowptr[d] + 1 + d_slot[i]] = src[i];
    }
}

// W^T bf16 precompute + zero-init of deg/pool: grid (128, 2), block 128
__global__ void k_prep_w(const float* __restrict__ W2, const float* __restrict__ W3) {
    int n = blockIdx.x, k = threadIdx.x, L = blockIdx.y;
    const float* W = (L == 0) ? W2 : W3;
    d_wthi[L][n * HIDDEN + k] = __float2bfloat16(W[k * HIDDEN + n]);
    int gt = (L * 128 + n) * 128 + k;          // 0..32767
    #pragma unroll
    for (int r = 0; r < 2; r++) {
        int p = gt + r * 32768;
        if (p < N_GRAPHS * HIDDEN) d_pool[p] = 0.f;
    }
    #pragma unroll
    for (int r = 0; r < 4; r++) {
        int p = gt + r * 32768;
        if (p < N_NODES) d_deg[p] = 0;
    }
}

// ---------------- layer 1: lane-per-edge gather + warp reduce + 7->128 GEMM ----------------
__global__ void k_layer1(const float* __restrict__ W1, const float* __restrict__ b1) {
    __shared__ float sW[IN_FEAT * HIDDEN];
    __shared__ float sb[HIDDEN];
    int tid = threadIdx.x;
    for (int i = tid; i < IN_FEAT * HIDDEN; i += 256) sW[i] = W1[i];
    if (tid < HIDDEN) sb[tid] = b1[tid];
    __syncthreads();

    int warp = (blockIdx.x * 256 + tid) >> 5;
    int lane = tid & 31;
    if (warp >= N_NODES) return;

    int beg = d_rowptr[warp], end = d_rowptr[warp + 1];
    float a[8];
    #pragma unroll
    for (int j = 0; j < 8; j++) a[j] = 0.f;

    for (int e = beg + lane; e < end; e += 32) {
        int s = d_csr_src[e];
        float4 q0 = *(const float4*)&d_xs[(size_t)s * 8];
        float4 q1 = *(const float4*)&d_xs[(size_t)s * 8 + 4];
        a[0] += q0.x; a[1] += q0.y; a[2] += q0.z; a[3] += q0.w;
        a[4] += q1.x; a[5] += q1.y; a[6] += q1.z; a[7] += q1.w;
    }
    #pragma unroll
    for (int o = 16; o > 0; o >>= 1) {
        #pragma unroll
        for (int j = 0; j < IN_FEAT; j++)
            a[j] += __shfl_xor_sync(0xffffffffu, a[j], o);
    }

    float dd = d_dis[warp];
    #pragma unroll
    for (int j = 0; j < IN_FEAT; j++) a[j] *= dd;

    int c0 = lane * 4;
    float4 o;
    o.x = sb[c0]; o.y = sb[c0 + 1]; o.z = sb[c0 + 2]; o.w = sb[c0 + 3];
    #pragma unroll
    for (int j = 0; j < IN_FEAT; j++) {
        o.x += a[j] * sW[j * HIDDEN + c0];
        o.y += a[j] * sW[j * HIDDEN + c0 + 1];
        o.z += a[j] * sW[j * HIDDEN + c0 + 2];
        o.w += a[j] * sW[j * HIDDEN + c0 + 3];
    }
    o.x = fmaxf(o.x, 0.f) * dd; o.y = fmaxf(o.y, 0.f) * dd;
    o.z = fmaxf(o.z, 0.f) * dd; o.w = fmaxf(o.w, 0.f) * dd;
    __nv_bfloat162 p[2];
    p[0] = __floats2bfloat162_rn(o.x, o.y);
    p[1] = __floats2bfloat162_rn(o.z, o.w);
    *(uint2*)&d_h1[(size_t)warp * HIDDEN + c0] = *(uint2*)p;
}

// ---------------- aggregation (bf16 in, fp32 out) ----------------
__global__ void k_aggregate(const __nv_bfloat16* __restrict__ hin, float* __restrict__ gout) {
    int warp = (blockIdx.x * blockDim.x + threadIdx.x) >> 5;
    int lane = threadIdx.x & 31;
    if (warp >= N_NODES) return;
    int beg = d_rowptr[warp], end = d_rowptr[warp + 1];
    float4 acc = make_float4(0.f, 0.f, 0.f, 0.f);
    int fo = lane * 4;
    for (int e0 = beg; e0 < end; e0 += 32) {
        int e = e0 + lane;
        int s = (e < end) ? d_csr_src[e] : 0;
        int cnt = min(32, end - e0);
        int j = 0;
        for (; j + 3 < cnt; j += 4) {
            int s0 = __shfl_sync(0xffffffffu, s, j);
            int s1 = __shfl_sync(0xffffffffu, s, j + 1);
            int s2 = __shfl_sync(0xffffffffu, s, j + 2);
            int s3 = __shfl_sync(0xffffffffu, s, j + 3);
            uint2 u0 = *(const uint2*)&hin[(size_t)s0 * HIDDEN + fo];
            uint2 u1 = *(const uint2*)&hin[(size_t)s1 * HIDDEN + fo];
            uint2 u2 = *(const uint2*)&hin[(size_t)s2 * HIDDEN + fo];
            uint2 u3 = *(const uint2*)&hin[(size_t)s3 * HIDDEN + fo];
            float2 a0 = __bfloat1622float2(*(__nv_bfloat162*)&u0.x);
            float2 b0 = __bfloat1622float2(*(__nv_bfloat162*)&u0.y);
            float2 a1 = __bfloat1622float2(*(__nv_bfloat162*)&u1.x);
            float2 b1 = __bfloat1622float2(*(__nv_bfloat162*)&u1.y);
            float2 a2 = __bfloat1622float2(*(__nv_bfloat162*)&u2.x);
            float2 b2 = __bfloat1622float2(*(__nv_bfloat162*)&u2.y);
            float2 a3 = __bfloat1622float2(*(__nv_bfloat162*)&u3.x);
            float2 b3 = __bfloat1622float2(*(__nv_bfloat162*)&u3.y);
            acc.x += (a0.x + a1.x) + (a2.x + a3.x);
            acc.y += (a0.y + a1.y) + (a2.y + a3.y);
            acc.z += (b0.x + b1.x) + (b2.x + b3.x);
            acc.w += (b0.y + b1.y) + (b2.y + b3.y);
        }
        for (; j < cnt; j++) {
            int s0 = __shfl_sync(0xffffffffu, s, j);
            uint2 u0 = *(const uint2*)&hin[(size_t)s0 * HIDDEN + fo];
            float2 a0 = __bfloat1622float2(*(__nv_bfloat162*)&u0.x);
            float2 b0 = __bfloat1622float2(*(__nv_bfloat162*)&u0.y);
            acc.x += a0.x; acc.y += a0.y; acc.z += b0.x; acc.w += b0.y;
        }
    }
    float dd = d_dis[warp];
    acc.x *= dd; acc.y *= dd; acc.z *= dd; acc.w *= dd;
    *(float4*)&gout[(size_t)warp * HIDDEN + fo] = acc;
}

// ---------------- HMMA GEMM: 64-row tile, 2-pass A-split (A_hi+A_lo) x W_hi ----------------
// mode=0: hout(bf16) = relu(G@W+b)*dis   |   mode=1: fused segment-max pooling
#define OFF_BIAS 0
#define OFF_AHI  1024
#define OFF_ALO  (1024 + 16384)
#define OFF_BHI  (1024 + 32768)
#define GEMM_MMA_SMEM (1024 + 32768 + 32768)

__global__ __launch_bounds__(256, 2)
void k_gemm_mma(const float* __restrict__ G, int wsel,
                const float* __restrict__ bias,
                __nv_bfloat16* __restrict__ hout,
                const int* __restrict__ batch, int mode) {
    extern __shared__ char smem[];
    uint32_t sbase = smem_u32(smem);
    float* sbias = (float*)(smem + OFF_BIAS);
    int tid = threadIdx.x, lane = tid & 31, wid = tid >> 5;
    int row0 = blockIdx.x * 64;

    if (tid < HIDDEN) sbias[tid] = bias[tid];

    // stage B: W^T hi [128 n][256B], swizzled
    {
        const uint4* bh = (const uint4*)&d_wthi[wsel][0];
        #pragma unroll
        for (int i = 0; i < 8; i++) {
            int v = tid + 256 * i;
            int n = v >> 4, c16 = v & 15;
            uint32_t off = SWZ(n, c16 * 16);
            *(uint4*)(smem + OFF_BHI + off) = bh[v];
        }
    }
    // stage A: 64 rows of fp32 G -> bf16 hi/lo, swizzled
    {
        const float4* G4 = (const float4*)G;
        #pragma unroll
        for (int i = 0; i < 4; i++) {
            int v = tid + 256 * i;
            int r = v >> 4, c16 = v & 15;
            int row = row0 + r;
            float f[8] = {0.f, 0.f, 0.f, 0.f, 0.f, 0.f, 0.f, 0.f};
            if (row < N_NODES) {
                float4 q0 = G4[(size_t)row * 32 + c16 * 2];
                float4 q1 = G4[(size_t)row * 32 + c16 * 2 + 1];
                f[0] = q0.x; f[1] = q0.y; f[2] = q0.z; f[3] = q0.w;
                f[4] = q1.x; f[5] = q1.y; f[6] = q1.z; f[7] = q1.w;
            }
            __nv_bfloat162 hi[4], lo[4];
            #pragma unroll
            for (int j = 0; j < 4; j++) {
                __nv_bfloat16 h0 = __float2bfloat16(f[2 * j]);
                __nv_bfloat16 h1 = __float2bfloat16(f[2 * j + 1]);
                hi[j] = __nv_bfloat162(h0, h1);
                lo[j] = __floats2bfloat162_rn(f[2 * j] - __bfloat162float(h0),
                                              f[2 * j + 1] - __bfloat162float(h1));
            }
            uint32_t off = SWZ(r, c16 * 16);
            *(uint4*)(smem + OFF_AHI + off) = *(uint4*)hi;
            *(uint4*)(smem + OFF_ALO + off) = *(uint4*)lo;
        }
    }
    __syncthreads();

    int mi = wid >> 1;          // m-tile 0..3
    int nb = (wid & 1) * 64;    // n-half

    int a_row = mi * 16 + (lane & 7) + ((lane >> 3) & 1) * 8;
    int a_kx  = ((lane >> 4) & 1) * 16;
    uint32_t a_base = sbase + (uint32_t)(a_row * 256);
    int a_swz = (a_row & 7) << 4;

    int b_row = nb + (lane & 7) + ((lane & 16) ? 8 : 0);
    int b_kx  = (lane & 8) ? 16 : 0;
    int b_swz = (b_row & 7) << 4;

    float acc[8][4];
    #pragma unroll
    for (int nt = 0; nt < 8; nt++)
        #pragma unroll
        for (int j = 0; j < 4; j++) acc[nt][j] = 0.f;

    const uint32_t a_offs[2] = {OFF_AHI, OFF_ALO};

    #pragma unroll
    for (int p = 0; p < 2; p++) {
        uint32_t abase = a_base + a_offs[p];
        #pragma unroll
        for (int ks = 0; ks < 8; ks++) {
            int kb = ks * 32;
            uint32_t a0r, a1r, a2r, a3r;
            LDMATRIX_X4(a0r, a1r, a2r, a3r, abase + (uint32_t)((kb + a_kx) ^ a_swz));
            uint32_t b[16];
            #pragma unroll
            for (int j = 0; j < 4; j++) {
                uint32_t addr = sbase + OFF_BHI + (uint32_t)((b_row + j * 16) * 256)
                              + (uint32_t)((kb + b_kx) ^ b_swz);
                LDMATRIX_X4(b[4 * j], b[4 * j + 1], b[4 * j + 2], b[4 * j + 3], addr);
            }
            #pragma unroll
            for (int nt = 0; nt < 8; nt++)
                MMA_BF16(acc[nt][0], acc[nt][1], acc[nt][2], acc[nt][3],
                         a0r, a1r, a2r, a3r, b[2 * nt], b[2 * nt + 1]);
        }
    }

    int q = lane & 3, rq = lane >> 2;
    int rA = mi * 16 + rq;          // local rows
    int rB = rA + 8;
    int rowA = row0 + rA;
    int rowB = row0 + rB;

    if (mode == 0) {
        float scA = (rowA < N_NODES) ? d_dis[rowA] : 1.f;
        float scB = (rowB < N_NODES) ? d_dis[rowB] : 1.f;
        #pragma unroll
        for (int nt = 0; nt < 8; nt++) {
            int col = nb + nt * 8 + 2 * q;
            float bc0 = sbias[col], bc1 = sbias[col + 1];
            if (rowA < N_NODES) {
                __nv_bfloat162 v = __floats2bfloat162_rn(fmaxf(acc[nt][0] + bc0, 0.f) * scA,
                                                         fmaxf(acc[nt][1] + bc1, 0.f) * scA);
                *(uint32_t*)&hout[(size_t)rowA * HIDDEN + col] = *(uint32_t*)&v;
            }
            if (rowB < N_NODES) {
                __nv_bfloat162 v = __floats2bfloat162_rn(fmaxf(acc[nt][2] + bc0, 0.f) * scB,
                                                         fmaxf(acc[nt][3] + bc1, 0.f) * scB);
                *(uint32_t*)&hout[(size_t)rowB * HIDDEN + col] = *(uint32_t*)&v;
            }
        }
    } else {
        // fused pooling: stage relu values into smem, run-length segment-max + atomicMax
        __syncthreads();
        float* spool = (float*)(smem + OFF_AHI);     // [64][128] fp32 = 32 KB
        int* sbatch = (int*)(smem + OFF_BHI);        // 64 ints (B is dead now)
        #pragma unroll
        for (int nt = 0; nt < 8; nt++) {
            int col = nb + nt * 8 + 2 * q;
            float bc0 = sbias[col], bc1 = sbias[col + 1];
            spool[rA * HIDDEN + col]     = fmaxf(acc[nt][0] + bc0, 0.f);
            spool[rA * HIDDEN + col + 1] = fmaxf(acc[nt][1] + bc1, 0.f);
            spool[rB * HIDDEN + col]     = fmaxf(acc[nt][2] + bc0, 0.f);
            spool[rB * HIDDEN + col + 1] = fmaxf(acc[nt][3] + bc1, 0.f);
        }
        if (tid < 64 && row0 + tid < N_NODES) sbatch[tid] = batch[row0 + tid];
        __syncthreads();
        if (tid < HIDDEN) {
            int cur = -1; float run = 0.f;
            #pragma unroll 4
            for (int r = 0; r < 64; r++) {
                if (row0 + r >= N_NODES) break;
                int g = sbatch[r];
                float v = spool[r * HIDDEN + tid];
                if (g != cur) {
                    if (cur >= 0)
                        atomicMax((int*)&d_pool[cur * HIDDEN + tid], __float_as_int(run));
                    cur = g; run = v;
                } else {
                    run = fmaxf(run, v);
                }
            }
            if (cur >= 0)
                atomicMax((int*)&d_pool[cur * HIDDEN + tid], __float_as_int(run));
        }
    }
}

// ---------------- final: warp-per-graph, out[512,2] = pooled @ Wl + bl ----------------
__global__ void k_final(const float* __restrict__ Wl, const float* __restrict__ bl,
                        float* __restrict__ out) {
    __shared__ float sW[HIDDEN * 2];
    __shared__ float sb[2];
    int tid = threadIdx.x;
    if (tid < HIDDEN * 2) sW[tid] = Wl[tid];
    if (tid < 2) sb[tid] = bl[tid];
    __syncthreads();

    int g = (blockIdx.x * 256 + tid) >> 5;    // graph id
    int lane = tid & 31;
    if (g >= N_GRAPHS) return;

    float4 p = *(const float4*)&d_pool[g * HIDDEN + lane * 4];
    int k0 = lane * 4;
    float a0 = p.x * sW[k0 * 2]     + p.y * sW[(k0 + 1) * 2]
             + p.z * sW[(k0 + 2) * 2] + p.w * sW[(k0 + 3) * 2];
    float a1 = p.x * sW[k0 * 2 + 1]     + p.y * sW[(k0 + 1) * 2 + 1]
             + p.z * sW[(k0 + 2) * 2 + 1] + p.w * sW[(k0 + 3) * 2 + 1];
    #pragma unroll
    for (int o = 16; o > 0; o >>= 1) {
        a0 += __shfl_xor_sync(0xffffffffu, a0, o);
        a1 += __shfl_xor_sync(0xffffffffu, a1, o);
    }
    if (lane == 0) {
        out[g * 2 + 0] = a0 + sb[0];
        out[g * 2 + 1] = a1 + sb[1];
    }
}

// ---------------- launcher ----------------
extern "C" void kernel_launch(void* const* d_in, const int* in_sizes, int n_in,
                              void* d_out, int out_size) {
    const float* x     = (const float*)d_in[0];
    const int*   ei    = (const int*)  d_in[1];
    const int*   batch = (const int*)  d_in[2];
    const float* W1 = (const float*)d_in[3];
    const float* b1 = (const float*)d_in[4];
    const float* W2 = (const float*)d_in[5];
    const float* b2 = (const float*)d_in[6];
    const float* W3 = (const float*)d_in[7];
    const float* b3 = (const float*)d_in[8];
    const float* Wl = (const float*)d_in[9];
    const float* bl = (const float*)d_in[10];
    float* out = (float*)d_out;

    const int* src = ei;
    const int* dst = ei + N_EDGES;

    __nv_bfloat16* h1; cudaGetSymbolAddress((void**)&h1, d_h1);
    __nv_bfloat16* h2; cudaGetSymbolAddress((void**)&h2, d_h2);
    float* agg;  cudaGetSymbolAddress((void**)&agg, d_agg);

    cudaFuncSetAttribute(k_gemm_mma, cudaFuncAttributeMaxDynamicSharedMemorySize, GEMM_MMA_SMEM);

    const int TPB = 256;

    k_prep_w      <<<dim3(128, 2), 128>>>(W2, W3);   // also zeroes d_deg / d_pool
    k_degree      <<<(N_EDGES / 4 + TPB - 1) / TPB, TPB>>>(dst);
    k_dis_scanpart<<<SCAN_BLOCKS, 1024>>>(x);
    k_scan_finish <<<SCAN_BLOCKS, 1024>>>();
    k_fill_edges  <<<(N_EDGES + TPB - 1) / TPB, TPB>>>(src, dst);

    // layer 1 -> h1 (bf16, dis-prescaled)
    k_layer1<<<(N_NODES * 32 + TPB - 1) / TPB, TPB>>>(W1, b1);

    // layer 2: agg = A h1 ; h2 = bf16(relu(agg W2 + b2) * dis)
    k_aggregate<<<(N_NODES * 32 + TPB - 1) / TPB, TPB>>>(h1, agg);
    k_gemm_mma<<<(N_NODES + 63) / 64, 256, GEMM_MMA_SMEM>>>(agg, 0, b2, h2, batch, 0);

    // layer 3: agg = A h2 ; fused GEMM + segment-max pooling
    k_aggregate<<<(N_NODES * 32 + TPB - 1) / TPB, TPB>>>(h2, agg);
    k_gemm_mma<<<(N_NODES + 63) / 64, 256, GEMM_MMA_SMEM>>>(agg, 1, b3, nullptr, batch, 1);

    k_final<<<(N_GRAPHS * 32 + TPB - 1) / TPB, TPB>>>(Wl, bl, out);
}